// round 1
// baseline (speedup 1.0000x reference)
#include <cuda_runtime.h>
#include <cstdint>

#define D_MODEL 768
#define N_LAT   16384
#define NROWS   8192
#define TOPK    32

// ---------------- device scratch (no allocs allowed) ----------------
__device__ float g_Wt[(size_t)N_LAT * D_MODEL];   // W_dec transposed: [N_LAT, D_MODEL]
__device__ int   g_sel_idx[NROWS * TOPK];
__device__ float g_sel_val[NROWS * TOPK];

// ---------------- packed f32x2 helpers ----------------
__device__ __forceinline__ unsigned long long pk2(float x) {
    unsigned long long r;
    asm("mov.b64 %0, {%1, %1};" : "=l"(r) : "f"(x));
    return r;
}
__device__ __forceinline__ void ffma2(unsigned long long& d, unsigned long long a, unsigned long long b) {
    asm("fma.rn.f32x2 %0, %1, %2, %0;" : "+l"(d) : "l"(a), "l"(b));
}
__device__ __forceinline__ float2 up2(unsigned long long v) {
    float2 f;
    asm("mov.b64 {%0, %1}, %2;" : "=f"(f.x), "=f"(f.y) : "l"(v));
    return f;
}

// ---------------- GEMM1: C[M,N] = A[M,K] * B[N,K]^T + bias[N] ----------------
// fp32 accuracy, packed f32x2 FMAs. 128x128 tile, BK=16, 256 thr, 8x8/thread.
#define BM 128
#define BN 128
#define BK 16

__global__ __launch_bounds__(256, 2) void gemm_xWT_bias(
    const float* __restrict__ A, const float* __restrict__ B,
    const float* __restrict__ bias, float* __restrict__ C,
    int M, int N, int K)
{
    __shared__ float As[BK][BM + 4];
    __shared__ float Bs[BK][BN + 4];

    const int bm = blockIdx.y * BM;
    const int bn = blockIdx.x * BN;
    const int tid = threadIdx.x;
    const int tx = tid & 15;   // N direction, 16
    const int ty = tid >> 4;   // M direction, 16

    unsigned long long acc[8][4];
#pragma unroll
    for (int i = 0; i < 8; i++)
#pragma unroll
        for (int j = 0; j < 4; j++) acc[i][j] = 0ULL;

    for (int k0 = 0; k0 < K; k0 += BK) {
#pragma unroll
        for (int p = 0; p < 2; p++) {
            int idx = tid + p * 256;
            int r = idx >> 2;
            int c4 = (idx & 3) * 4;
            float4 va = *(const float4*)&A[(size_t)(bm + r) * K + k0 + c4];
            As[c4 + 0][r] = va.x; As[c4 + 1][r] = va.y;
            As[c4 + 2][r] = va.z; As[c4 + 3][r] = va.w;
            float4 vb = *(const float4*)&B[(size_t)(bn + r) * K + k0 + c4];
            Bs[c4 + 0][r] = vb.x; Bs[c4 + 1][r] = vb.y;
            Bs[c4 + 2][r] = vb.z; Bs[c4 + 3][r] = vb.w;
        }
        __syncthreads();

#pragma unroll
        for (int k = 0; k < BK; k++) {
            float4 a0 = *(const float4*)&As[k][ty * 8];
            float4 a1 = *(const float4*)&As[k][ty * 8 + 4];
            const unsigned long long* bp = (const unsigned long long*)&Bs[k][tx * 8];
            unsigned long long b0 = bp[0], b1 = bp[1], b2 = bp[2], b3 = bp[3];
            unsigned long long ap[8];
            ap[0] = pk2(a0.x); ap[1] = pk2(a0.y); ap[2] = pk2(a0.z); ap[3] = pk2(a0.w);
            ap[4] = pk2(a1.x); ap[5] = pk2(a1.y); ap[6] = pk2(a1.z); ap[7] = pk2(a1.w);
#pragma unroll
            for (int i = 0; i < 8; i++) {
                ffma2(acc[i][0], ap[i], b0);
                ffma2(acc[i][1], ap[i], b1);
                ffma2(acc[i][2], ap[i], b2);
                ffma2(acc[i][3], ap[i], b3);
            }
        }
        __syncthreads();
    }

    // epilogue: + bias, store
    float bv[8];
#pragma unroll
    for (int j = 0; j < 8; j++) bv[j] = bias[bn + tx * 8 + j];

#pragma unroll
    for (int i = 0; i < 8; i++) {
        int row = bm + ty * 8 + i;
        float2 p0 = up2(acc[i][0]);
        float2 p1 = up2(acc[i][1]);
        float2 p2 = up2(acc[i][2]);
        float2 p3 = up2(acc[i][3]);
        float4 o0 = make_float4(p0.x + bv[0], p0.y + bv[1], p1.x + bv[2], p1.y + bv[3]);
        float4 o1 = make_float4(p2.x + bv[4], p2.y + bv[5], p3.x + bv[6], p3.y + bv[7]);
        float* cp = &C[(size_t)row * N + bn + tx * 8];
        *(float4*)cp = o0;
        *(float4*)(cp + 4) = o1;
    }
}

// ---------------- top-k(32) per row via 2-level radix select ----------------
__global__ __launch_bounds__(256) void topk_kernel(
    const float* __restrict__ pre, float* __restrict__ latents)
{
    extern __shared__ unsigned su[];   // N_LAT monotone-mapped keys
    __shared__ unsigned hist[2048];
    __shared__ int chunk[256];
    __shared__ int s_b1, s_c1, s_b2, s_c2;
    __shared__ int s_nc, s_nsel, s_neq;
    __shared__ unsigned s_ukth;
    __shared__ unsigned cand[256];
    __shared__ int sel_i[TOPK];
    __shared__ int eq_i[64];

    const int row = blockIdx.x;
    const int tid = threadIdx.x;
    const float* prow = pre + (size_t)row * N_LAT;

    for (int i = tid; i < N_LAT; i += 256) {
        unsigned b = __float_as_uint(prow[i]);
        su[i] = (b & 0x80000000u) ? ~b : (b | 0x80000000u);
    }
    for (int i = tid; i < 2048; i += 256) hist[i] = 0u;
    if (tid == 0) { s_nc = 0; s_nsel = 0; s_neq = 0; }
    __syncthreads();

    // pass 1: top 11 bits
    for (int i = tid; i < N_LAT; i += 256) atomicAdd(&hist[su[i] >> 21], 1u);
    __syncthreads();
    { int s = 0;
#pragma unroll
      for (int j = 0; j < 8; j++) s += (int)hist[tid * 8 + j];
      chunk[tid] = s; }
    __syncthreads();
    if (tid == 0) {
        int cum = 0, b1 = 0, c1 = 0;
        for (int c = 255; c >= 0; --c) {
            if (cum + chunk[c] >= TOPK) {
                for (int b = c * 8 + 7;; --b) {
                    if (cum + (int)hist[b] >= TOPK) { b1 = b; c1 = cum; break; }
                    cum += (int)hist[b];
                }
                break;
            }
            cum += chunk[c];
        }
        s_b1 = b1; s_c1 = c1;
    }
    __syncthreads();
    const int b1 = s_b1;
    const int target1 = TOPK - s_c1;

    // pass 2: next 11 bits within bin b1
    for (int i = tid; i < 2048; i += 256) hist[i] = 0u;
    __syncthreads();
    for (int i = tid; i < N_LAT; i += 256) {
        unsigned u = su[i];
        if ((int)(u >> 21) == b1) atomicAdd(&hist[(u >> 10) & 2047u], 1u);
    }
    __syncthreads();
    { int s = 0;
#pragma unroll
      for (int j = 0; j < 8; j++) s += (int)hist[tid * 8 + j];
      chunk[tid] = s; }
    __syncthreads();
    if (tid == 0) {
        int cum = 0, b2 = 0, c2 = 0;
        for (int c = 255; c >= 0; --c) {
            if (cum + chunk[c] >= target1) {
                for (int b = c * 8 + 7;; --b) {
                    if (cum + (int)hist[b] >= target1) { b2 = b; c2 = cum; break; }
                    cum += (int)hist[b];
                }
                break;
            }
            cum += chunk[c];
        }
        s_b2 = b2; s_c2 = c2;
    }
    __syncthreads();
    const unsigned pref = ((unsigned)b1 << 11) | (unsigned)s_b2;
    const int target2 = target1 - s_c2;   // >= 1

    // collect candidates sharing the 21-bit prefix
    for (int i = tid; i < N_LAT; i += 256) {
        unsigned u = su[i];
        if ((u >> 10) == pref) {
            int p = atomicAdd(&s_nc, 1);
            if (p < 256) cand[p] = u;
        }
    }
    __syncthreads();
    if (tid == 0) {
        int nc = s_nc < 256 ? s_nc : 256;
        unsigned long long cur = 0x100000000ULL;
        int need = target2;
        unsigned ukth = 0u;
        for (;;) {
            unsigned best = 0u; int cnt = 0; bool any = false;
            for (int i = 0; i < nc; i++) {
                unsigned u = cand[i];
                if ((unsigned long long)u < cur) {
                    if (!any || u > best) { best = u; cnt = 1; any = true; }
                    else if (u == best) cnt++;
                }
            }
            if (need <= cnt || !any) { ukth = best; break; }
            need -= cnt; cur = (unsigned long long)best;
        }
        s_ukth = ukth;
    }
    __syncthreads();
    const unsigned ukth = s_ukth;

    // final selection: strictly greater -> in; ties at ukth -> lowest indices first
    for (int i = tid; i < N_LAT; i += 256) {
        unsigned u = su[i];
        if (u > ukth) {
            int p = atomicAdd(&s_nsel, 1);
            sel_i[p] = i;
        } else if (u == ukth) {
            int p = atomicAdd(&s_neq, 1);
            if (p < 64) eq_i[p] = i;
        }
    }
    __syncthreads();
    if (tid == 0) {
        int ns = s_nsel;
        int ne = s_neq < 64 ? s_neq : 64;
        int need = TOPK - ns;
        for (int t = 0; t < need; t++) {
            int bi = -1, bv = 0x7FFFFFFF;
            for (int i = 0; i < ne; i++) {
                int v = eq_i[i];
                if (v >= 0 && v < bv) { bv = v; bi = i; }
            }
            eq_i[bi] = -1;
            sel_i[ns + t] = bv;
        }
    }
    __syncthreads();

    for (int p = tid; p < TOPK; p += 256) {
        int idx = sel_i[p];
        unsigned u = su[idx];
        unsigned bits = (u & 0x80000000u) ? (u ^ 0x80000000u) : ~u;
        float v = __uint_as_float(bits);
        float rv = v > 0.f ? v : 0.f;
        latents[(size_t)row * N_LAT + idx] = rv;
        g_sel_idx[row * TOPK + p] = idx;
        g_sel_val[row * TOPK + p] = rv;
    }
}

// ---------------- W_dec transpose: [D_MODEL, N_LAT] -> g_Wt [N_LAT, D_MODEL] ----------------
__global__ void transpose_kernel(const float* __restrict__ W)
{
    __shared__ float t[32][33];
    const int j0 = blockIdx.x * 32;
    const int d0 = blockIdx.y * 32;
    const int tx = threadIdx.x;
    const int ty0 = threadIdx.y;
#pragma unroll
    for (int s = 0; s < 32; s += 8) {
        int ty = ty0 + s;
        t[ty][tx] = W[(size_t)(d0 + ty) * N_LAT + j0 + tx];
    }
    __syncthreads();
#pragma unroll
    for (int s = 0; s < 32; s += 8) {
        int ty = ty0 + s;
        g_Wt[(size_t)(j0 + ty) * D_MODEL + d0 + tx] = t[tx][ty];
    }
}

// ---------------- sparse decode: recon = latents @ W_dec^T + b_dec ----------------
__global__ __launch_bounds__(256) void recon_kernel(
    const float* __restrict__ b_dec, float* __restrict__ recon)
{
    __shared__ int sidx[TOPK];
    __shared__ float sval[TOPK];
    const int row = blockIdx.x;
    const int tid = threadIdx.x;
    if (tid < TOPK) {
        sidx[tid] = g_sel_idx[row * TOPK + tid];
        sval[tid] = g_sel_val[row * TOPK + tid];
    }
    __syncthreads();
    float a0 = 0.f, a1 = 0.f, a2 = 0.f;
#pragma unroll 4
    for (int k = 0; k < TOPK; k++) {
        float v = sval[k];
        const float* w = &g_Wt[(size_t)sidx[k] * D_MODEL];
        a0 += v * w[tid];
        a1 += v * w[tid + 256];
        a2 += v * w[tid + 512];
    }
    const size_t o = (size_t)row * D_MODEL;
    recon[o + tid]       = a0 + b_dec[tid];
    recon[o + tid + 256] = a1 + b_dec[tid + 256];
    recon[o + tid + 512] = a2 + b_dec[tid + 512];
}

// ---------------- launch ----------------
extern "C" void kernel_launch(void* const* d_in, const int* in_sizes, int n_in,
                              void* d_out, int out_size)
{
    const float* x  = (const float*)d_in[0];
    const float* We = (const float*)d_in[1];
    const float* be = (const float*)d_in[2];
    const float* Wd = (const float*)d_in[3];
    const float* bd = (const float*)d_in[4];

    float* out     = (float*)d_out;
    float* latents = out;
    float* recon   = out + (size_t)NROWS * N_LAT;
    float* pre     = recon + (size_t)NROWS * D_MODEL;

    cudaMemsetAsync(latents, 0, (size_t)NROWS * N_LAT * sizeof(float));

    transpose_kernel<<<dim3(N_LAT / 32, D_MODEL / 32), dim3(32, 8)>>>(Wd);

    gemm_xWT_bias<<<dim3(N_LAT / BN, NROWS / BM), 256>>>(x, We, be, pre,
                                                         NROWS, N_LAT, D_MODEL);

    cudaFuncSetAttribute(topk_kernel, cudaFuncAttributeMaxDynamicSharedMemorySize,
                         N_LAT * (int)sizeof(unsigned));
    topk_kernel<<<NROWS, 256, N_LAT * sizeof(unsigned)>>>(pre, latents);

    recon_kernel<<<NROWS, 256>>>(bd, recon);
}

// round 4
// speedup vs baseline: 1.0794x; 1.0794x over previous
#include <cuda_runtime.h>
#include <cuda_fp16.h>
#include <cstdint>

#define D_MODEL 768
#define N_LAT   16384
#define NROWS   8192
#define TOPK    32
#define NCAND   48

// ---------------- device scratch (no allocs allowed) ----------------
__device__ int   g_sel_idx[NROWS * TOPK];
__device__ float g_sel_val[NROWS * TOPK];
__device__ int   g_cand[NROWS * NCAND];
__device__ float g_Wt[(size_t)N_LAT * D_MODEL];           // W_dec transposed
__device__ __half g_x1[(size_t)NROWS * D_MODEL];          // fp16 split of x
__device__ __half g_x2[(size_t)NROWS * D_MODEL];
__device__ __half g_w1[(size_t)N_LAT * D_MODEL];          // fp16 split of W_enc*256
__device__ __half g_w2[(size_t)N_LAT * D_MODEL];

__device__ __forceinline__ uint32_t smem_u32(const void* p) {
    uint32_t a;
    asm("{ .reg .u64 t; cvta.to.shared.u64 t, %1; cvt.u32.u64 %0, t; }" : "=r"(a) : "l"(p));
    return a;
}

// =====================================================================
// split-convert kernels (memory-bound, run once per call)
// =====================================================================
__global__ __launch_bounds__(256) void convert_x(const float* __restrict__ x)
{
    int i = blockIdx.x * 256 + threadIdx.x;        // index into float4 view
    float4 v = ((const float4*)x)[i];
    half h0 = __float2half_rn(v.x), h1 = __float2half_rn(v.y);
    half h2 = __float2half_rn(v.z), h3 = __float2half_rn(v.w);
    half g0 = __float2half_rn(v.x - __half2float(h0));
    half g1 = __float2half_rn(v.y - __half2float(h1));
    half g2 = __float2half_rn(v.z - __half2float(h2));
    half g3 = __float2half_rn(v.w - __half2float(h3));
    __half2 a = __halves2half2(h0, h1), b = __halves2half2(h2, h3);
    __half2 c = __halves2half2(g0, g1), d = __halves2half2(g2, g3);
    ((uint2*)g_x1)[i] = make_uint2(*(uint32_t*)&a, *(uint32_t*)&b);
    ((uint2*)g_x2)[i] = make_uint2(*(uint32_t*)&c, *(uint32_t*)&d);
}

__global__ __launch_bounds__(256) void convert_w(const float* __restrict__ W)
{
    int i = blockIdx.x * 256 + threadIdx.x;
    float4 v = ((const float4*)W)[i];
    v.x *= 256.f; v.y *= 256.f; v.z *= 256.f; v.w *= 256.f;
    half h0 = __float2half_rn(v.x), h1 = __float2half_rn(v.y);
    half h2 = __float2half_rn(v.z), h3 = __float2half_rn(v.w);
    half g0 = __float2half_rn(v.x - __half2float(h0));
    half g1 = __float2half_rn(v.y - __half2float(h1));
    half g2 = __float2half_rn(v.z - __half2float(h2));
    half g3 = __float2half_rn(v.w - __half2float(h3));
    __half2 a = __halves2half2(h0, h1), b = __halves2half2(h2, h3);
    __half2 c = __halves2half2(g0, g1), d = __halves2half2(g2, g3);
    ((uint2*)g_w1)[i] = make_uint2(*(uint32_t*)&a, *(uint32_t*)&b);
    ((uint2*)g_w2)[i] = make_uint2(*(uint32_t*)&c, *(uint32_t*)&d);
}

// =====================================================================
// GEMM1: pre[8192,16384] = x @ W_enc^T + b_enc via mma.sync fp16 3-split
// CTA 128x128, BK=32, 8 warps (2x4), 3-stage cp.async pipeline.
// =====================================================================
#define GSTAGES 3
#define GBK 32
#define ROWB 80
#define TILEB (128 * ROWB)
#define STAGEB (4 * TILEB)
#define GEMM_SMEM (GSTAGES * STAGEB)

__device__ __forceinline__ void ldsm4(uint32_t& r0, uint32_t& r1, uint32_t& r2, uint32_t& r3,
                                      uint32_t addr) {
    asm volatile("ldmatrix.sync.aligned.m8n8.x4.shared.b16 {%0,%1,%2,%3}, [%4];"
                 : "=r"(r0), "=r"(r1), "=r"(r2), "=r"(r3) : "r"(addr));
}
__device__ __forceinline__ void mma16816(float* c, const uint32_t* a, const uint32_t* b) {
    asm volatile("mma.sync.aligned.m16n8k16.row.col.f32.f16.f16.f32 "
                 "{%0,%1,%2,%3}, {%4,%5,%6,%7}, {%8,%9}, {%0,%1,%2,%3};"
                 : "+f"(c[0]), "+f"(c[1]), "+f"(c[2]), "+f"(c[3])
                 : "r"(a[0]), "r"(a[1]), "r"(a[2]), "r"(a[3]), "r"(b[0]), "r"(b[1]));
}
__device__ __forceinline__ void cpasync16(uint32_t dst, const void* src) {
    asm volatile("cp.async.cg.shared.global [%0], [%1], 16;" :: "r"(dst), "l"(src));
}

__global__ __launch_bounds__(256, 1) void gemm_mma(
    const float* __restrict__ bias, float* __restrict__ C)
{
    extern __shared__ char sm[];
    const uint32_t sb = smem_u32(sm);
    const int tid = threadIdx.x;
    const int bm = blockIdx.y * 128;
    const int bn = blockIdx.x * 128;
    const int lane = tid & 31;
    const int warp = tid >> 5;
    const int wm = warp & 1;
    const int wn = warp >> 1;

    float acc[4][4][4];
#pragma unroll
    for (int i = 0; i < 4; i++)
#pragma unroll
        for (int j = 0; j < 4; j++)
#pragma unroll
            for (int q = 0; q < 4; q++) acc[i][j][q] = 0.f;

    const __half* ax1 = g_x1 + (size_t)bm * D_MODEL;
    const __half* ax2 = g_x2 + (size_t)bm * D_MODEL;
    const __half* bw1 = g_w1 + (size_t)bn * D_MODEL;
    const __half* bw2 = g_w2 + (size_t)bn * D_MODEL;

    auto load_stage = [&](int s, int c) {
        const int k0 = c * GBK;
#pragma unroll
        for (int i = 0; i < 8; ++i) {
            int idx = tid + i * 256;
            int t = idx >> 9;
            int rem = idx & 511;
            int row = rem >> 2, ch = rem & 3;
            uint32_t dst = sb + s * STAGEB + t * TILEB + row * ROWB + ch * 16;
            const __half* base = (t == 0) ? ax1 : (t == 1) ? ax2 : (t == 2) ? bw1 : bw2;
            const __half* src = base + (size_t)row * D_MODEL + k0 + ch * 8;
            cpasync16(dst, src);
        }
    };

    const int NCH = D_MODEL / GBK;   // 24
    load_stage(0, 0);
    asm volatile("cp.async.commit_group;");
    load_stage(1, 1);
    asm volatile("cp.async.commit_group;");

    const uint32_t a_row = (uint32_t)(wm * 64 + (lane & 7) + ((lane >> 3) & 1) * 8);
    const uint32_t a_off = a_row * ROWB + ((lane >> 4) * 16);
    const uint32_t b_row = (uint32_t)(wn * 32 + (lane & 7) + ((lane >> 4) & 1) * 8);
    const uint32_t b_off = b_row * ROWB + (((lane >> 3) & 1) * 16);

    for (int c = 0; c < NCH; ++c) {
        asm volatile("cp.async.wait_group %0;" :: "n"(1));
        __syncthreads();
        if (c + 2 < NCH) load_stage((c + 2) % GSTAGES, c + 2);
        asm volatile("cp.async.commit_group;");

        const uint32_t stg = sb + (c % GSTAGES) * STAGEB;
#pragma unroll
        for (int kg = 0; kg < 2; ++kg) {
            const uint32_t kgo = kg * 32;
            uint32_t af[4][4], bf1[4][2], bf2[4][2];
#pragma unroll
            for (int mt = 0; mt < 4; ++mt)
                ldsm4(af[mt][0], af[mt][1], af[mt][2], af[mt][3],
                      stg + 0 * TILEB + a_off + mt * 16 * ROWB + kgo);
#pragma unroll
            for (int q = 0; q < 2; ++q) {
                ldsm4(bf1[2 * q][0], bf1[2 * q][1], bf1[2 * q + 1][0], bf1[2 * q + 1][1],
                      stg + 2 * TILEB + b_off + q * 16 * ROWB + kgo);
                ldsm4(bf2[2 * q][0], bf2[2 * q][1], bf2[2 * q + 1][0], bf2[2 * q + 1][1],
                      stg + 3 * TILEB + b_off + q * 16 * ROWB + kgo);
            }
#pragma unroll
            for (int mt = 0; mt < 4; ++mt)
#pragma unroll
                for (int nt = 0; nt < 4; ++nt) mma16816(acc[mt][nt], af[mt], bf1[nt]);
#pragma unroll
            for (int mt = 0; mt < 4; ++mt)
#pragma unroll
                for (int nt = 0; nt < 4; ++nt) mma16816(acc[mt][nt], af[mt], bf2[nt]);
#pragma unroll
            for (int mt = 0; mt < 4; ++mt)
                ldsm4(af[mt][0], af[mt][1], af[mt][2], af[mt][3],
                      stg + 1 * TILEB + a_off + mt * 16 * ROWB + kgo);
#pragma unroll
            for (int mt = 0; mt < 4; ++mt)
#pragma unroll
                for (int nt = 0; nt < 4; ++nt) mma16816(acc[mt][nt], af[mt], bf1[nt]);
        }
        __syncthreads();
    }

    const float s = 1.f / 256.f;
#pragma unroll
    for (int nt = 0; nt < 4; ++nt) {
        const int col = bn + wn * 32 + nt * 8 + (lane & 3) * 2;
        const float2 bv = *(const float2*)&bias[col];
#pragma unroll
        for (int mt = 0; mt < 4; ++mt) {
            const int row = bm + wm * 64 + mt * 16 + (lane >> 2);
            float2 v0 = make_float2(fmaf(acc[mt][nt][0], s, bv.x),
                                    fmaf(acc[mt][nt][1], s, bv.y));
            float2 v1 = make_float2(fmaf(acc[mt][nt][2], s, bv.x),
                                    fmaf(acc[mt][nt][3], s, bv.y));
            *(float2*)&C[(size_t)row * N_LAT + col] = v0;
            *(float2*)&C[(size_t)(row + 8) * N_LAT + col] = v1;
        }
    }
}

// =====================================================================
// candidate selection: approximate top-NCAND per row via 2-level radix
// =====================================================================
__global__ __launch_bounds__(256) void topk_kernel(const float* __restrict__ pre)
{
    extern __shared__ unsigned su[];
    __shared__ unsigned hist[2048];
    __shared__ int chunk[256];
    __shared__ int s_b1, s_c1, s_b2, s_c2;
    __shared__ int s_nc, s_nsel;
    __shared__ unsigned s_ukth;
    __shared__ unsigned cand[256];

    const int row = blockIdx.x;
    const int tid = threadIdx.x;
    const float* prow = pre + (size_t)row * N_LAT;

    for (int i = tid; i < N_LAT; i += 256) {
        unsigned b = __float_as_uint(prow[i]);
        su[i] = (b & 0x80000000u) ? ~b : (b | 0x80000000u);
    }
    for (int i = tid; i < 2048; i += 256) hist[i] = 0u;
    if (tid == 0) { s_nc = 0; s_nsel = 0; }
    __syncthreads();

    for (int i = tid; i < N_LAT; i += 256) atomicAdd(&hist[su[i] >> 21], 1u);
    __syncthreads();
    { int s = 0;
#pragma unroll
      for (int j = 0; j < 8; j++) s += (int)hist[tid * 8 + j];
      chunk[tid] = s; }
    __syncthreads();
    if (tid == 0) {
        int cum = 0, b1 = 0, c1 = 0;
        for (int c = 255; c >= 0; --c) {
            if (cum + chunk[c] >= NCAND) {
                for (int b = c * 8 + 7;; --b) {
                    if (cum + (int)hist[b] >= NCAND) { b1 = b; c1 = cum; break; }
                    cum += (int)hist[b];
                }
                break;
            }
            cum += chunk[c];
        }
        s_b1 = b1; s_c1 = c1;
    }
    __syncthreads();
    const int b1 = s_b1;
    const int target1 = NCAND - s_c1;

    for (int i = tid; i < 2048; i += 256) hist[i] = 0u;
    __syncthreads();
    for (int i = tid; i < N_LAT; i += 256) {
        unsigned u = su[i];
        if ((int)(u >> 21) == b1) atomicAdd(&hist[(u >> 10) & 2047u], 1u);
    }
    __syncthreads();
    { int s = 0;
#pragma unroll
      for (int j = 0; j < 8; j++) s += (int)hist[tid * 8 + j];
      chunk[tid] = s; }
    __syncthreads();
    if (tid == 0) {
        int cum = 0, b2 = 0, c2 = 0;
        for (int c = 255; c >= 0; --c) {
            if (cum + chunk[c] >= target1) {
                for (int b = c * 8 + 7;; --b) {
                    if (cum + (int)hist[b] >= target1) { b2 = b; c2 = cum; break; }
                    cum += (int)hist[b];
                }
                break;
            }
            cum += chunk[c];
        }
        s_b2 = b2; s_c2 = c2;
    }
    __syncthreads();
    const unsigned pref = ((unsigned)b1 << 11) | (unsigned)s_b2;
    const int target2 = target1 - s_c2;

    for (int i = tid; i < N_LAT; i += 256) {
        unsigned u = su[i];
        if ((u >> 10) == pref) {
            int p = atomicAdd(&s_nc, 1);
            if (p < 256) cand[p] = u;
        }
    }
    __syncthreads();
    if (tid == 0) {
        int nc = s_nc < 256 ? s_nc : 256;
        unsigned long long cur = 0x100000000ULL;
        int need = target2;
        unsigned ukth = 0u;
        for (;;) {
            unsigned best = 0u; int cnt = 0; bool any = false;
            for (int i = 0; i < nc; i++) {
                unsigned u = cand[i];
                if ((unsigned long long)u < cur) {
                    if (!any || u > best) { best = u; cnt = 1; any = true; }
                    else if (u == best) cnt++;
                }
            }
            if (need <= cnt || !any) { ukth = best; break; }
            need -= cnt; cur = (unsigned long long)best;
        }
        s_ukth = ukth;
    }
    __syncthreads();
    const unsigned ukth = s_ukth;

    // strictly-greater first, then fill with equals (order within set irrelevant)
    for (int i = tid; i < N_LAT; i += 256) {
        if (su[i] > ukth) {
            int p = atomicAdd(&s_nsel, 1);
            g_cand[row * NCAND + p] = i;
        }
    }
    __syncthreads();
    for (int i = tid; i < N_LAT; i += 256) {
        if (su[i] == ukth) {
            int p = atomicAdd(&s_nsel, 1);
            if (p < NCAND) g_cand[row * NCAND + p] = i;
        }
    }
}

// =====================================================================
// refine: recompute NCAND candidate dots in double, exact top-32 select
// =====================================================================
__global__ __launch_bounds__(256) void refine_kernel(
    const float* __restrict__ x, const float* __restrict__ We,
    const float* __restrict__ be, float* __restrict__ latents)
{
    __shared__ float xs[D_MODEL];
    __shared__ float cv[NCAND];
    __shared__ int   ci[NCAND];
    const int row = blockIdx.x;
    const int tid = threadIdx.x;
    const int lane = tid & 31, warp = tid >> 5;

    for (int j = tid; j < D_MODEL; j += 256) xs[j] = x[(size_t)row * D_MODEL + j];
    if (tid < NCAND) ci[tid] = g_cand[row * NCAND + tid];
    __syncthreads();

    for (int c = warp; c < NCAND; c += 8) {
        const int idx = ci[c];
        const float* wr = We + (size_t)idx * D_MODEL;
        double acc = 0.0;
#pragma unroll 4
        for (int j = lane; j < D_MODEL; j += 32)
            acc += (double)xs[j] * (double)wr[j];
#pragma unroll
        for (int o = 16; o > 0; o >>= 1)
            acc += __shfl_down_sync(0xffffffffu, acc, o);
        if (lane == 0) cv[c] = (float)(acc + (double)be[idx]);
    }
    __syncthreads();

    if (tid < NCAND) {
        const float v = cv[tid];
        const int idx = ci[tid];
        int r = 0;
#pragma unroll
        for (int j = 0; j < NCAND; ++j) {
            float u = cv[j];
            r += (u > v) || (u == v && ci[j] < idx);
        }
        if (r < TOPK) {
            float rv = v > 0.f ? v : 0.f;
            latents[(size_t)row * N_LAT + idx] = rv;
            g_sel_idx[row * TOPK + r] = idx;
            g_sel_val[row * TOPK + r] = rv;
        }
    }
}

// ---------------- W_dec transpose ----------------
__global__ void transpose_kernel(const float* __restrict__ W)
{
    __shared__ float t[32][33];
    const int j0 = blockIdx.x * 32;
    const int d0 = blockIdx.y * 32;
    const int tx = threadIdx.x;
    const int ty0 = threadIdx.y;
#pragma unroll
    for (int s = 0; s < 32; s += 8) {
        int ty = ty0 + s;
        t[ty][tx] = W[(size_t)(d0 + ty) * N_LAT + j0 + tx];
    }
    __syncthreads();
#pragma unroll
    for (int s = 0; s < 32; s += 8) {
        int ty = ty0 + s;
        g_Wt[(size_t)(j0 + ty) * D_MODEL + d0 + tx] = t[tx][ty];
    }
}

// ---------------- sparse decode ----------------
__global__ __launch_bounds__(256) void recon_kernel(
    const float* __restrict__ b_dec, float* __restrict__ recon)
{
    __shared__ int sidx[TOPK];
    __shared__ float sval[TOPK];
    const int row = blockIdx.x;
    const int tid = threadIdx.x;
    if (tid < TOPK) {
        sidx[tid] = g_sel_idx[row * TOPK + tid];
        sval[tid] = g_sel_val[row * TOPK + tid];
    }
    __syncthreads();
    float a0 = 0.f, a1 = 0.f, a2 = 0.f;
#pragma unroll 4
    for (int k = 0; k < TOPK; k++) {
        float v = sval[k];
        const float* w = &g_Wt[(size_t)sidx[k] * D_MODEL];
        a0 += v * w[tid];
        a1 += v * w[tid + 256];
        a2 += v * w[tid + 512];
    }
    const size_t o = (size_t)row * D_MODEL;
    recon[o + tid]       = a0 + b_dec[tid];
    recon[o + tid + 256] = a1 + b_dec[tid + 256];
    recon[o + tid + 512] = a2 + b_dec[tid + 512];
}

// ---------------- launch ----------------
extern "C" void kernel_launch(void* const* d_in, const int* in_sizes, int n_in,
                              void* d_out, int out_size)
{
    const float* x  = (const float*)d_in[0];
    const float* We = (const float*)d_in[1];
    const float* be = (const float*)d_in[2];
    const float* Wd = (const float*)d_in[3];
    const float* bd = (const float*)d_in[4];

    float* out     = (float*)d_out;
    float* latents = out;
    float* recon   = out + (size_t)NROWS * N_LAT;
    float* pre     = recon + (size_t)NROWS * D_MODEL;

    cudaMemsetAsync(latents, 0, (size_t)NROWS * N_LAT * sizeof(float));

    convert_x<<<NROWS * D_MODEL / 4 / 256, 256>>>(x);
    convert_w<<<N_LAT * D_MODEL / 4 / 256, 256>>>(We);
    transpose_kernel<<<dim3(N_LAT / 32, D_MODEL / 32), dim3(32, 8)>>>(Wd);

    cudaFuncSetAttribute(gemm_mma, cudaFuncAttributeMaxDynamicSharedMemorySize, GEMM_SMEM);
    gemm_mma<<<dim3(N_LAT / 128, NROWS / 128), 256, GEMM_SMEM>>>(be, pre);

    cudaFuncSetAttribute(topk_kernel, cudaFuncAttributeMaxDynamicSharedMemorySize,
                         N_LAT * (int)sizeof(unsigned));
    topk_kernel<<<NROWS, 256, N_LAT * sizeof(unsigned)>>>(pre);

    refine_kernel<<<NROWS, 256>>>(x, We, be, latents);

    recon_kernel<<<NROWS, 256>>>(bd, recon);
}

// round 5
// speedup vs baseline: 1.3236x; 1.2262x over previous
#include <cuda_runtime.h>
#include <cuda_fp16.h>
#include <cstdint>

#define D_MODEL 768
#define N_LAT   16384
#define NROWS   8192
#define TOPK    32
#define NCAND   48

// ---------------- device scratch (no allocs allowed) ----------------
__device__ int   g_sel_idx[NROWS * TOPK];
__device__ float g_sel_val[NROWS * TOPK];
__device__ int   g_cand[NROWS * NCAND];
__device__ float g_Wt[(size_t)N_LAT * D_MODEL];           // W_dec transposed
__device__ __half g_x1[(size_t)NROWS * D_MODEL];          // fp16 split of x
__device__ __half g_x2[(size_t)NROWS * D_MODEL];
__device__ __half g_w1[(size_t)N_LAT * D_MODEL];          // fp16(W_enc), single

__device__ __forceinline__ uint32_t smem_u32(const void* p) {
    uint32_t a;
    asm("{ .reg .u64 t; cvta.to.shared.u64 t, %1; cvt.u32.u64 %0, t; }" : "=r"(a) : "l"(p));
    return a;
}

// =====================================================================
// split-convert kernels
// =====================================================================
__global__ __launch_bounds__(256) void convert_x(const float* __restrict__ x)
{
    int i = blockIdx.x * 256 + threadIdx.x;
    float4 v = ((const float4*)x)[i];
    half h0 = __float2half_rn(v.x), h1 = __float2half_rn(v.y);
    half h2 = __float2half_rn(v.z), h3 = __float2half_rn(v.w);
    half g0 = __float2half_rn(v.x - __half2float(h0));
    half g1 = __float2half_rn(v.y - __half2float(h1));
    half g2 = __float2half_rn(v.z - __half2float(h2));
    half g3 = __float2half_rn(v.w - __half2float(h3));
    __half2 a = __halves2half2(h0, h1), b = __halves2half2(h2, h3);
    __half2 c = __halves2half2(g0, g1), d = __halves2half2(g2, g3);
    ((uint2*)g_x1)[i] = make_uint2(*(uint32_t*)&a, *(uint32_t*)&b);
    ((uint2*)g_x2)[i] = make_uint2(*(uint32_t*)&c, *(uint32_t*)&d);
}

__global__ __launch_bounds__(256) void convert_w(const float* __restrict__ W)
{
    int i = blockIdx.x * 256 + threadIdx.x;
    float4 v = ((const float4*)W)[i];
    __half2 a = __halves2half2(__float2half_rn(v.x), __float2half_rn(v.y));
    __half2 b = __halves2half2(__float2half_rn(v.z), __float2half_rn(v.w));
    ((uint2*)g_w1)[i] = make_uint2(*(uint32_t*)&a, *(uint32_t*)&b);
}

// =====================================================================
// GEMM1: pre = x @ W_enc^T + b_enc, fp16 2-term (x1*w + x2*w)
// CTA 128x128, BK=64, 16 warps (4x4, warp tile 32x32), 3-stage cp.async.
// =====================================================================
#define GBK 64
#define ROWB 144                       // 64 halves (128B) padded to 144B
#define TILEB (128 * ROWB)             // 18432
#define STAGEB (3 * TILEB)             // A1 A2 B
#define GSTAGES 3
#define GEMM_SMEM (GSTAGES * STAGEB)   // 165888

__device__ __forceinline__ void ldsm4(uint32_t& r0, uint32_t& r1, uint32_t& r2, uint32_t& r3,
                                      uint32_t addr) {
    asm volatile("ldmatrix.sync.aligned.m8n8.x4.shared.b16 {%0,%1,%2,%3}, [%4];"
                 : "=r"(r0), "=r"(r1), "=r"(r2), "=r"(r3) : "r"(addr));
}
__device__ __forceinline__ void mma16816(float* c, const uint32_t* a, const uint32_t* b) {
    asm volatile("mma.sync.aligned.m16n8k16.row.col.f32.f16.f16.f32 "
                 "{%0,%1,%2,%3}, {%4,%5,%6,%7}, {%8,%9}, {%0,%1,%2,%3};"
                 : "+f"(c[0]), "+f"(c[1]), "+f"(c[2]), "+f"(c[3])
                 : "r"(a[0]), "r"(a[1]), "r"(a[2]), "r"(a[3]), "r"(b[0]), "r"(b[1]));
}
__device__ __forceinline__ void cpasync16(uint32_t dst, const void* src) {
    asm volatile("cp.async.cg.shared.global [%0], [%1], 16;" :: "r"(dst), "l"(src));
}

__global__ __launch_bounds__(512, 1) void gemm_mma(
    const float* __restrict__ bias, float* __restrict__ C)
{
    extern __shared__ char sm[];
    const uint32_t sb = smem_u32(sm);
    const int tid = threadIdx.x;
    const int bm = blockIdx.y * 128;
    const int bn = blockIdx.x * 128;
    const int lane = tid & 31;
    const int warp = tid >> 5;
    const int wm = warp & 3;          // 4 -> 32 rows each
    const int wn = warp >> 2;         // 4 -> 32 cols each

    float acc[2][4][4];
#pragma unroll
    for (int i = 0; i < 2; i++)
#pragma unroll
        for (int j = 0; j < 4; j++)
#pragma unroll
            for (int q = 0; q < 4; q++) acc[i][j][q] = 0.f;

    const __half* ax1 = g_x1 + (size_t)bm * D_MODEL;
    const __half* ax2 = g_x2 + (size_t)bm * D_MODEL;
    const __half* bw  = g_w1 + (size_t)bn * D_MODEL;

    auto load_stage = [&](int s, int c) {
        const int k0 = c * GBK;
#pragma unroll
        for (int i = 0; i < 6; ++i) {
            int idx = tid + i * 512;              // 3072 chunks of 16B
            int t = idx >> 10;                    // 0:A1 1:A2 2:B
            int rem = idx & 1023;
            int row = rem >> 3, ch = rem & 7;
            uint32_t dst = sb + s * STAGEB + t * TILEB + row * ROWB + ch * 16;
            const __half* base = (t == 0) ? ax1 : (t == 1) ? ax2 : bw;
            cpasync16(dst, base + (size_t)row * D_MODEL + k0 + ch * 8);
        }
    };

    const int NCH = D_MODEL / GBK;   // 12
    load_stage(0, 0);
    asm volatile("cp.async.commit_group;");
    load_stage(1, 1);
    asm volatile("cp.async.commit_group;");

    const uint32_t a_row = (uint32_t)(wm * 32 + (lane & 7) + ((lane >> 3) & 1) * 8);
    const uint32_t a_off = a_row * ROWB + ((lane >> 4) * 16);
    const uint32_t b_row = (uint32_t)(wn * 32 + (lane & 7) + ((lane >> 4) & 1) * 8);
    const uint32_t b_off = b_row * ROWB + (((lane >> 3) & 1) * 16);

    for (int c = 0; c < NCH; ++c) {
        asm volatile("cp.async.wait_group %0;" :: "n"(1));
        __syncthreads();
        if (c + 2 < NCH) load_stage((c + 2) % GSTAGES, c + 2);
        asm volatile("cp.async.commit_group;");

        const uint32_t stg = sb + (c % GSTAGES) * STAGEB;
#pragma unroll
        for (int kg = 0; kg < 4; ++kg) {
            const uint32_t kgo = kg * 32;
            uint32_t af1[2][4], af2[2][4], bf[4][2];
#pragma unroll
            for (int mt = 0; mt < 2; ++mt) {
                ldsm4(af1[mt][0], af1[mt][1], af1[mt][2], af1[mt][3],
                      stg + 0 * TILEB + a_off + mt * 16 * ROWB + kgo);
                ldsm4(af2[mt][0], af2[mt][1], af2[mt][2], af2[mt][3],
                      stg + 1 * TILEB + a_off + mt * 16 * ROWB + kgo);
            }
#pragma unroll
            for (int q = 0; q < 2; ++q)
                ldsm4(bf[2 * q][0], bf[2 * q][1], bf[2 * q + 1][0], bf[2 * q + 1][1],
                      stg + 2 * TILEB + b_off + q * 16 * ROWB + kgo);
#pragma unroll
            for (int mt = 0; mt < 2; ++mt)
#pragma unroll
                for (int nt = 0; nt < 4; ++nt) mma16816(acc[mt][nt], af1[mt], bf[nt]);
#pragma unroll
            for (int mt = 0; mt < 2; ++mt)
#pragma unroll
                for (int nt = 0; nt < 4; ++nt) mma16816(acc[mt][nt], af2[mt], bf[nt]);
        }
        __syncthreads();
    }

    // ---- epilogue: add bias, store ----
#pragma unroll
    for (int nt = 0; nt < 4; ++nt) {
        const int col = bn + wn * 32 + nt * 8 + (lane & 3) * 2;
        const float2 bv = *(const float2*)&bias[col];
#pragma unroll
        for (int mt = 0; mt < 2; ++mt) {
            const int row = bm + wm * 32 + mt * 16 + (lane >> 2);
            float2 v0 = make_float2(acc[mt][nt][0] + bv.x, acc[mt][nt][1] + bv.y);
            float2 v1 = make_float2(acc[mt][nt][2] + bv.x, acc[mt][nt][3] + bv.y);
            *(float2*)&C[(size_t)row * N_LAT + col] = v0;
            *(float2*)&C[(size_t)(row + 8) * N_LAT + col] = v1;
        }
    }
}

// =====================================================================
// candidate selection: approximate top-NCAND per row via 2-level radix
// =====================================================================
__global__ __launch_bounds__(256) void topk_kernel(const float* __restrict__ pre)
{
    extern __shared__ unsigned su[];
    __shared__ unsigned hist[2048];
    __shared__ int chunk[256];
    __shared__ int s_b1, s_c1, s_b2, s_c2;
    __shared__ int s_nc, s_nsel;
    __shared__ unsigned s_ukth;
    __shared__ unsigned cand[256];

    const int row = blockIdx.x;
    const int tid = threadIdx.x;
    const float* prow = pre + (size_t)row * N_LAT;

    for (int i = tid; i < N_LAT; i += 256) {
        unsigned b = __float_as_uint(prow[i]);
        su[i] = (b & 0x80000000u) ? ~b : (b | 0x80000000u);
    }
    for (int i = tid; i < 2048; i += 256) hist[i] = 0u;
    if (tid == 0) { s_nc = 0; s_nsel = 0; }
    __syncthreads();

    for (int i = tid; i < N_LAT; i += 256) atomicAdd(&hist[su[i] >> 21], 1u);
    __syncthreads();
    { int s = 0;
#pragma unroll
      for (int j = 0; j < 8; j++) s += (int)hist[tid * 8 + j];
      chunk[tid] = s; }
    __syncthreads();
    if (tid == 0) {
        int cum = 0, b1 = 0, c1 = 0;
        for (int c = 255; c >= 0; --c) {
            if (cum + chunk[c] >= NCAND) {
                for (int b = c * 8 + 7;; --b) {
                    if (cum + (int)hist[b] >= NCAND) { b1 = b; c1 = cum; break; }
                    cum += (int)hist[b];
                }
                break;
            }
            cum += chunk[c];
        }
        s_b1 = b1; s_c1 = c1;
    }
    __syncthreads();
    const int b1 = s_b1;
    const int target1 = NCAND - s_c1;

    for (int i = tid; i < 2048; i += 256) hist[i] = 0u;
    __syncthreads();
    for (int i = tid; i < N_LAT; i += 256) {
        unsigned u = su[i];
        if ((int)(u >> 21) == b1) atomicAdd(&hist[(u >> 10) & 2047u], 1u);
    }
    __syncthreads();
    { int s = 0;
#pragma unroll
      for (int j = 0; j < 8; j++) s += (int)hist[tid * 8 + j];
      chunk[tid] = s; }
    __syncthreads();
    if (tid == 0) {
        int cum = 0, b2 = 0, c2 = 0;
        for (int c = 255; c >= 0; --c) {
            if (cum + chunk[c] >= target1) {
                for (int b = c * 8 + 7;; --b) {
                    if (cum + (int)hist[b] >= target1) { b2 = b; c2 = cum; break; }
                    cum += (int)hist[b];
                }
                break;
            }
            cum += chunk[c];
        }
        s_b2 = b2; s_c2 = c2;
    }
    __syncthreads();
    const unsigned pref = ((unsigned)b1 << 11) | (unsigned)s_b2;
    const int target2 = target1 - s_c2;

    for (int i = tid; i < N_LAT; i += 256) {
        unsigned u = su[i];
        if ((u >> 10) == pref) {
            int p = atomicAdd(&s_nc, 1);
            if (p < 256) cand[p] = u;
        }
    }
    __syncthreads();
    if (tid == 0) {
        int nc = s_nc < 256 ? s_nc : 256;
        unsigned long long cur = 0x100000000ULL;
        int need = target2;
        unsigned ukth = 0u;
        for (;;) {
            unsigned best = 0u; int cnt = 0; bool any = false;
            for (int i = 0; i < nc; i++) {
                unsigned u = cand[i];
                if ((unsigned long long)u < cur) {
                    if (!any || u > best) { best = u; cnt = 1; any = true; }
                    else if (u == best) cnt++;
                }
            }
            if (need <= cnt || !any) { ukth = best; break; }
            need -= cnt; cur = (unsigned long long)best;
        }
        s_ukth = ukth;
    }
    __syncthreads();
    const unsigned ukth = s_ukth;

    for (int i = tid; i < N_LAT; i += 256) {
        if (su[i] > ukth) {
            int p = atomicAdd(&s_nsel, 1);
            g_cand[row * NCAND + p] = i;
        }
    }
    __syncthreads();
    for (int i = tid; i < N_LAT; i += 256) {
        if (su[i] == ukth) {
            int p = atomicAdd(&s_nsel, 1);
            if (p < NCAND) g_cand[row * NCAND + p] = i;
        }
    }
}

// =====================================================================
// refine: recompute NCAND candidate dots in double, exact top-32 select
// =====================================================================
__global__ __launch_bounds__(256) void refine_kernel(
    const float* __restrict__ x, const float* __restrict__ We,
    const float* __restrict__ be, float* __restrict__ latents)
{
    __shared__ float xs[D_MODEL];
    __shared__ float cv[NCAND];
    __shared__ int   ci[NCAND];
    const int row = blockIdx.x;
    const int tid = threadIdx.x;
    const int lane = tid & 31, warp = tid >> 5;

    for (int j = tid; j < D_MODEL; j += 256) xs[j] = x[(size_t)row * D_MODEL + j];
    if (tid < NCAND) ci[tid] = g_cand[row * NCAND + tid];
    __syncthreads();

    for (int c = warp; c < NCAND; c += 8) {
        const int idx = ci[c];
        const float* wr = We + (size_t)idx * D_MODEL;
        double acc = 0.0;
#pragma unroll 4
        for (int j = lane; j < D_MODEL; j += 32)
            acc += (double)xs[j] * (double)wr[j];
#pragma unroll
        for (int o = 16; o > 0; o >>= 1)
            acc += __shfl_down_sync(0xffffffffu, acc, o);
        if (lane == 0) cv[c] = (float)(acc + (double)be[idx]);
    }
    __syncthreads();

    if (tid < NCAND) {
        const float v = cv[tid];
        const int idx = ci[tid];
        int r = 0;
#pragma unroll
        for (int j = 0; j < NCAND; ++j) {
            float u = cv[j];
            r += (u > v) || (u == v && ci[j] < idx);
        }
        if (r < TOPK) {
            float rv = v > 0.f ? v : 0.f;
            latents[(size_t)row * N_LAT + idx] = rv;
            g_sel_idx[row * TOPK + r] = idx;
            g_sel_val[row * TOPK + r] = rv;
        }
    }
}

// ---------------- W_dec transpose ----------------
__global__ void transpose_kernel(const float* __restrict__ W)
{
    __shared__ float t[32][33];
    const int j0 = blockIdx.x * 32;
    const int d0 = blockIdx.y * 32;
    const int tx = threadIdx.x;
    const int ty0 = threadIdx.y;
#pragma unroll
    for (int s = 0; s < 32; s += 8) {
        int ty = ty0 + s;
        t[ty][tx] = W[(size_t)(d0 + ty) * N_LAT + j0 + tx];
    }
    __syncthreads();
#pragma unroll
    for (int s = 0; s < 32; s += 8) {
        int ty = ty0 + s;
        g_Wt[(size_t)(j0 + ty) * D_MODEL + d0 + tx] = t[tx][ty];
    }
}

// ---------------- sparse decode ----------------
__global__ __launch_bounds__(256) void recon_kernel(
    const float* __restrict__ b_dec, float* __restrict__ recon)
{
    __shared__ int sidx[TOPK];
    __shared__ float sval[TOPK];
    const int row = blockIdx.x;
    const int tid = threadIdx.x;
    if (tid < TOPK) {
        sidx[tid] = g_sel_idx[row * TOPK + tid];
        sval[tid] = g_sel_val[row * TOPK + tid];
    }
    __syncthreads();
    float a0 = 0.f, a1 = 0.f, a2 = 0.f;
#pragma unroll 4
    for (int k = 0; k < TOPK; k++) {
        float v = sval[k];
        const float* w = &g_Wt[(size_t)sidx[k] * D_MODEL];
        a0 += v * w[tid];
        a1 += v * w[tid + 256];
        a2 += v * w[tid + 512];
    }
    const size_t o = (size_t)row * D_MODEL;
    recon[o + tid]       = a0 + b_dec[tid];
    recon[o + tid + 256] = a1 + b_dec[tid + 256];
    recon[o + tid + 512] = a2 + b_dec[tid + 512];
}

// ---------------- launch ----------------
extern "C" void kernel_launch(void* const* d_in, const int* in_sizes, int n_in,
                              void* d_out, int out_size)
{
    const float* x  = (const float*)d_in[0];
    const float* We = (const float*)d_in[1];
    const float* be = (const float*)d_in[2];
    const float* Wd = (const float*)d_in[3];
    const float* bd = (const float*)d_in[4];

    float* out     = (float*)d_out;
    float* latents = out;
    float* recon   = out + (size_t)NROWS * N_LAT;
    float* pre     = recon + (size_t)NROWS * D_MODEL;

    cudaMemsetAsync(latents, 0, (size_t)NROWS * N_LAT * sizeof(float));

    convert_x<<<NROWS * D_MODEL / 4 / 256, 256>>>(x);
    convert_w<<<N_LAT * D_MODEL / 4 / 256, 256>>>(We);
    transpose_kernel<<<dim3(N_LAT / 32, D_MODEL / 32), dim3(32, 8)>>>(Wd);

    cudaFuncSetAttribute(gemm_mma, cudaFuncAttributeMaxDynamicSharedMemorySize, GEMM_SMEM);
    gemm_mma<<<dim3(N_LAT / 128, NROWS / 128), 512, GEMM_SMEM>>>(be, pre);

    cudaFuncSetAttribute(topk_kernel, cudaFuncAttributeMaxDynamicSharedMemorySize,
                         N_LAT * (int)sizeof(unsigned));
    topk_kernel<<<NROWS, 256, N_LAT * sizeof(unsigned)>>>(pre);

    refine_kernel<<<NROWS, 256>>>(x, We, be, latents);

    recon_kernel<<<NROWS, 256>>>(bd, recon);
}

// round 6
// speedup vs baseline: 1.6055x; 1.2130x over previous
#include <cuda_runtime.h>
#include <cuda_fp16.h>
#include <cstdint>

#define D_MODEL 768
#define N_LAT   16384
#define NROWS   8192
#define TOPK    32
#define NCAND   48

// ---------------- device scratch (no allocs allowed) ----------------
__device__ int   g_sel_idx[NROWS * TOPK];
__device__ float g_sel_val[NROWS * TOPK];
__device__ int   g_cand[NROWS * NCAND];
__device__ float g_Wt[(size_t)N_LAT * D_MODEL];           // W_dec transposed
__device__ __half g_x1[(size_t)NROWS * D_MODEL];          // fp16(x)
__device__ __half g_w1[(size_t)N_LAT * D_MODEL];          // fp16(W_enc)

__device__ __forceinline__ uint32_t smem_u32(const void* p) {
    uint32_t a;
    asm("{ .reg .u64 t; cvta.to.shared.u64 t, %1; cvt.u32.u64 %0, t; }" : "=r"(a) : "l"(p));
    return a;
}

// =====================================================================
// convert kernels (memory-bound, run once per call)
// =====================================================================
__global__ __launch_bounds__(256) void convert_x(const float* __restrict__ x)
{
    int i = blockIdx.x * 256 + threadIdx.x;
    float4 v = ((const float4*)x)[i];
    __half2 a = __halves2half2(__float2half_rn(v.x), __float2half_rn(v.y));
    __half2 b = __halves2half2(__float2half_rn(v.z), __float2half_rn(v.w));
    ((uint2*)g_x1)[i] = make_uint2(*(uint32_t*)&a, *(uint32_t*)&b);
}

__global__ __launch_bounds__(256) void convert_w(const float* __restrict__ W)
{
    int i = blockIdx.x * 256 + threadIdx.x;
    float4 v = ((const float4*)W)[i];
    __half2 a = __halves2half2(__float2half_rn(v.x), __float2half_rn(v.y));
    __half2 b = __halves2half2(__float2half_rn(v.z), __float2half_rn(v.w));
    ((uint2*)g_w1)[i] = make_uint2(*(uint32_t*)&a, *(uint32_t*)&b);
}

// =====================================================================
// GEMM1: pre = x @ W_enc^T + b_enc, single fp16 MMA, fp32 accum
// CTA 128x128, BK=64, 8 warps (2x4, warp tile 64x32), 2-stage cp.async,
// 73.7KB smem -> 2 CTAs/SM.
// =====================================================================
#define GBK 64
#define ROWB 144                       // 64 halves (128B) padded to 144B
#define TILEB (128 * ROWB)             // 18432
#define STAGEB (2 * TILEB)             // A B
#define GSTAGES 2
#define GEMM_SMEM (GSTAGES * STAGEB)   // 73728

__device__ __forceinline__ void ldsm4(uint32_t& r0, uint32_t& r1, uint32_t& r2, uint32_t& r3,
                                      uint32_t addr) {
    asm volatile("ldmatrix.sync.aligned.m8n8.x4.shared.b16 {%0,%1,%2,%3}, [%4];"
                 : "=r"(r0), "=r"(r1), "=r"(r2), "=r"(r3) : "r"(addr));
}
__device__ __forceinline__ void mma16816(float* c, const uint32_t* a, const uint32_t* b) {
    asm volatile("mma.sync.aligned.m16n8k16.row.col.f32.f16.f16.f32 "
                 "{%0,%1,%2,%3}, {%4,%5,%6,%7}, {%8,%9}, {%0,%1,%2,%3};"
                 : "+f"(c[0]), "+f"(c[1]), "+f"(c[2]), "+f"(c[3])
                 : "r"(a[0]), "r"(a[1]), "r"(a[2]), "r"(a[3]), "r"(b[0]), "r"(b[1]));
}
__device__ __forceinline__ void cpasync16(uint32_t dst, const void* src) {
    asm volatile("cp.async.cg.shared.global [%0], [%1], 16;" :: "r"(dst), "l"(src));
}

__global__ __launch_bounds__(256, 2) void gemm_mma(
    const float* __restrict__ bias, float* __restrict__ C)
{
    extern __shared__ char sm[];
    const uint32_t sb = smem_u32(sm);
    const int tid = threadIdx.x;
    const int bm = blockIdx.y * 128;
    const int bn = blockIdx.x * 128;
    const int lane = tid & 31;
    const int warp = tid >> 5;
    const int wm = warp & 1;          // 2 -> 64 rows each
    const int wn = warp >> 1;         // 4 -> 32 cols each

    float acc[4][4][4];
#pragma unroll
    for (int i = 0; i < 4; i++)
#pragma unroll
        for (int j = 0; j < 4; j++)
#pragma unroll
            for (int q = 0; q < 4; q++) acc[i][j][q] = 0.f;

    const __half* ax = g_x1 + (size_t)bm * D_MODEL;
    const __half* bw = g_w1 + (size_t)bn * D_MODEL;

    auto load_stage = [&](int s, int c) {
        const int k0 = c * GBK;
#pragma unroll
        for (int i = 0; i < 8; ++i) {
            int idx = tid + i * 256;              // 2048 chunks of 16B
            int t = idx >> 10;                    // 0:A 1:B
            int rem = idx & 1023;
            int row = rem >> 3, ch = rem & 7;
            uint32_t dst = sb + s * STAGEB + t * TILEB + row * ROWB + ch * 16;
            const __half* base = (t == 0) ? ax : bw;
            cpasync16(dst, base + (size_t)row * D_MODEL + k0 + ch * 8);
        }
    };

    const int NCH = D_MODEL / GBK;   // 12
    load_stage(0, 0);
    asm volatile("cp.async.commit_group;");
    load_stage(1, 1);
    asm volatile("cp.async.commit_group;");

    const uint32_t a_row = (uint32_t)(wm * 64 + (lane & 7) + ((lane >> 3) & 1) * 8);
    const uint32_t a_off = a_row * ROWB + ((lane >> 4) * 16);
    const uint32_t b_row = (uint32_t)(wn * 32 + (lane & 7) + ((lane >> 4) & 1) * 8);
    const uint32_t b_off = b_row * ROWB + (((lane >> 3) & 1) * 16);

    for (int c = 0; c < NCH; ++c) {
        asm volatile("cp.async.wait_group %0;" :: "n"(1));
        __syncthreads();

        const uint32_t stg = sb + (c & 1) * STAGEB;
#pragma unroll
        for (int kg = 0; kg < 4; ++kg) {
            const uint32_t kgo = kg * 32;
            uint32_t af[4][4], bf[4][2];
#pragma unroll
            for (int mt = 0; mt < 4; ++mt)
                ldsm4(af[mt][0], af[mt][1], af[mt][2], af[mt][3],
                      stg + 0 * TILEB + a_off + mt * 16 * ROWB + kgo);
#pragma unroll
            for (int q = 0; q < 2; ++q)
                ldsm4(bf[2 * q][0], bf[2 * q][1], bf[2 * q + 1][0], bf[2 * q + 1][1],
                      stg + 1 * TILEB + b_off + q * 16 * ROWB + kgo);
#pragma unroll
            for (int mt = 0; mt < 4; ++mt)
#pragma unroll
                for (int nt = 0; nt < 4; ++nt) mma16816(acc[mt][nt], af[mt], bf[nt]);
        }
        __syncthreads();
        if (c + 2 < NCH) load_stage(c & 1, c + 2);
        asm volatile("cp.async.commit_group;");
    }

    // ---- epilogue: add bias, store ----
#pragma unroll
    for (int nt = 0; nt < 4; ++nt) {
        const int col = bn + wn * 32 + nt * 8 + (lane & 3) * 2;
        const float2 bv = *(const float2*)&bias[col];
#pragma unroll
        for (int mt = 0; mt < 4; ++mt) {
            const int row = bm + wm * 64 + mt * 16 + (lane >> 2);
            float2 v0 = make_float2(acc[mt][nt][0] + bv.x, acc[mt][nt][1] + bv.y);
            float2 v1 = make_float2(acc[mt][nt][2] + bv.x, acc[mt][nt][3] + bv.y);
            *(float2*)&C[(size_t)row * N_LAT + col] = v0;
            *(float2*)&C[(size_t)(row + 8) * N_LAT + col] = v1;
        }
    }
}

// =====================================================================
// candidate selection: approximate top-NCAND per row via 2-level radix
// =====================================================================
__global__ __launch_bounds__(256) void topk_kernel(const float* __restrict__ pre)
{
    extern __shared__ unsigned su[];
    __shared__ unsigned hist[2048];
    __shared__ int chunk[256];
    __shared__ int s_b1, s_c1, s_b2, s_c2;
    __shared__ int s_nc, s_nsel;
    __shared__ unsigned s_ukth;
    __shared__ unsigned cand[256];

    const int row = blockIdx.x;
    const int tid = threadIdx.x;
    const float* prow = pre + (size_t)row * N_LAT;

    for (int i = tid; i < N_LAT; i += 256) {
        unsigned b = __float_as_uint(prow[i]);
        su[i] = (b & 0x80000000u) ? ~b : (b | 0x80000000u);
    }
    for (int i = tid; i < 2048; i += 256) hist[i] = 0u;
    if (tid == 0) { s_nc = 0; s_nsel = 0; }
    __syncthreads();

    for (int i = tid; i < N_LAT; i += 256) atomicAdd(&hist[su[i] >> 21], 1u);
    __syncthreads();
    { int s = 0;
#pragma unroll
      for (int j = 0; j < 8; j++) s += (int)hist[tid * 8 + j];
      chunk[tid] = s; }
    __syncthreads();
    if (tid == 0) {
        int cum = 0, b1 = 0, c1 = 0;
        for (int c = 255; c >= 0; --c) {
            if (cum + chunk[c] >= NCAND) {
                for (int b = c * 8 + 7;; --b) {
                    if (cum + (int)hist[b] >= NCAND) { b1 = b; c1 = cum; break; }
                    cum += (int)hist[b];
                }
                break;
            }
            cum += chunk[c];
        }
        s_b1 = b1; s_c1 = c1;
    }
    __syncthreads();
    const int b1 = s_b1;
    const int target1 = NCAND - s_c1;

    for (int i = tid; i < 2048; i += 256) hist[i] = 0u;
    __syncthreads();
    for (int i = tid; i < N_LAT; i += 256) {
        unsigned u = su[i];
        if ((int)(u >> 21) == b1) atomicAdd(&hist[(u >> 10) & 2047u], 1u);
    }
    __syncthreads();
    { int s = 0;
#pragma unroll
      for (int j = 0; j < 8; j++) s += (int)hist[tid * 8 + j];
      chunk[tid] = s; }
    __syncthreads();
    if (tid == 0) {
        int cum = 0, b2 = 0, c2 = 0;
        for (int c = 255; c >= 0; --c) {
            if (cum + chunk[c] >= target1) {
                for (int b = c * 8 + 7;; --b) {
                    if (cum + (int)hist[b] >= target1) { b2 = b; c2 = cum; break; }
                    cum += (int)hist[b];
                }
                break;
            }
            cum += chunk[c];
        }
        s_b2 = b2; s_c2 = c2;
    }
    __syncthreads();
    const unsigned pref = ((unsigned)b1 << 11) | (unsigned)s_b2;
    const int target2 = target1 - s_c2;

    for (int i = tid; i < N_LAT; i += 256) {
        unsigned u = su[i];
        if ((u >> 10) == pref) {
            int p = atomicAdd(&s_nc, 1);
            if (p < 256) cand[p] = u;
        }
    }
    __syncthreads();
    if (tid == 0) {
        int nc = s_nc < 256 ? s_nc : 256;
        unsigned long long cur = 0x100000000ULL;
        int need = target2;
        unsigned ukth = 0u;
        for (;;) {
            unsigned best = 0u; int cnt = 0; bool any = false;
            for (int i = 0; i < nc; i++) {
                unsigned u = cand[i];
                if ((unsigned long long)u < cur) {
                    if (!any || u > best) { best = u; cnt = 1; any = true; }
                    else if (u == best) cnt++;
                }
            }
            if (need <= cnt || !any) { ukth = best; break; }
            need -= cnt; cur = (unsigned long long)best;
        }
        s_ukth = ukth;
    }
    __syncthreads();
    const unsigned ukth = s_ukth;

    for (int i = tid; i < N_LAT; i += 256) {
        if (su[i] > ukth) {
            int p = atomicAdd(&s_nsel, 1);
            g_cand[row * NCAND + p] = i;
        }
    }
    __syncthreads();
    for (int i = tid; i < N_LAT; i += 256) {
        if (su[i] == ukth) {
            int p = atomicAdd(&s_nsel, 1);
            if (p < NCAND) g_cand[row * NCAND + p] = i;
        }
    }
}

// =====================================================================
// refine: recompute NCAND candidate dots in double, exact top-32 select
// =====================================================================
__global__ __launch_bounds__(256) void refine_kernel(
    const float* __restrict__ x, const float* __restrict__ We,
    const float* __restrict__ be, float* __restrict__ latents)
{
    __shared__ float xs[D_MODEL];
    __shared__ float cv[NCAND];
    __shared__ int   ci[NCAND];
    const int row = blockIdx.x;
    const int tid = threadIdx.x;
    const int lane = tid & 31, warp = tid >> 5;

    for (int j = tid; j < D_MODEL; j += 256) xs[j] = x[(size_t)row * D_MODEL + j];
    if (tid < NCAND) ci[tid] = g_cand[row * NCAND + tid];
    __syncthreads();

    for (int c = warp; c < NCAND; c += 8) {
        const int idx = ci[c];
        const float* wr = We + (size_t)idx * D_MODEL;
        double acc = 0.0;
#pragma unroll 4
        for (int j = lane; j < D_MODEL; j += 32)
            acc += (double)xs[j] * (double)wr[j];
#pragma unroll
        for (int o = 16; o > 0; o >>= 1)
            acc += __shfl_down_sync(0xffffffffu, acc, o);
        if (lane == 0) cv[c] = (float)(acc + (double)be[idx]);
    }
    __syncthreads();

    if (tid < NCAND) {
        const float v = cv[tid];
        const int idx = ci[tid];
        int r = 0;
#pragma unroll
        for (int j = 0; j < NCAND; ++j) {
            float u = cv[j];
            r += (u > v) || (u == v && ci[j] < idx);
        }
        if (r < TOPK) {
            float rv = v > 0.f ? v : 0.f;
            latents[(size_t)row * N_LAT + idx] = rv;
            g_sel_idx[row * TOPK + r] = idx;
            g_sel_val[row * TOPK + r] = rv;
        }
    }
}

// ---------------- W_dec transpose ----------------
__global__ void transpose_kernel(const float* __restrict__ W)
{
    __shared__ float t[32][33];
    const int j0 = blockIdx.x * 32;
    const int d0 = blockIdx.y * 32;
    const int tx = threadIdx.x;
    const int ty0 = threadIdx.y;
#pragma unroll
    for (int s = 0; s < 32; s += 8) {
        int ty = ty0 + s;
        t[ty][tx] = W[(size_t)(d0 + ty) * N_LAT + j0 + tx];
    }
    __syncthreads();
#pragma unroll
    for (int s = 0; s < 32; s += 8) {
        int ty = ty0 + s;
        g_Wt[(size_t)(j0 + ty) * D_MODEL + d0 + tx] = t[tx][ty];
    }
}

// ---------------- sparse decode ----------------
__global__ __launch_bounds__(256) void recon_kernel(
    const float* __restrict__ b_dec, float* __restrict__ recon)
{
    __shared__ int sidx[TOPK];
    __shared__ float sval[TOPK];
    const int row = blockIdx.x;
    const int tid = threadIdx.x;
    if (tid < TOPK) {
        sidx[tid] = g_sel_idx[row * TOPK + tid];
        sval[tid] = g_sel_val[row * TOPK + tid];
    }
    __syncthreads();
    float a0 = 0.f, a1 = 0.f, a2 = 0.f;
#pragma unroll 4
    for (int k = 0; k < TOPK; k++) {
        float v = sval[k];
        const float* w = &g_Wt[(size_t)sidx[k] * D_MODEL];
        a0 += v * w[tid];
        a1 += v * w[tid + 256];
        a2 += v * w[tid + 512];
    }
    const size_t o = (size_t)row * D_MODEL;
    recon[o + tid]       = a0 + b_dec[tid];
    recon[o + tid + 256] = a1 + b_dec[tid + 256];
    recon[o + tid + 512] = a2 + b_dec[tid + 512];
}

// ---------------- launch ----------------
extern "C" void kernel_launch(void* const* d_in, const int* in_sizes, int n_in,
                              void* d_out, int out_size)
{
    const float* x  = (const float*)d_in[0];
    const float* We = (const float*)d_in[1];
    const float* be = (const float*)d_in[2];
    const float* Wd = (const float*)d_in[3];
    const float* bd = (const float*)d_in[4];

    float* out     = (float*)d_out;
    float* latents = out;
    float* recon   = out + (size_t)NROWS * N_LAT;
    float* pre     = recon + (size_t)NROWS * D_MODEL;

    cudaMemsetAsync(latents, 0, (size_t)NROWS * N_LAT * sizeof(float));

    convert_x<<<NROWS * D_MODEL / 4 / 256, 256>>>(x);
    convert_w<<<N_LAT * D_MODEL / 4 / 256, 256>>>(We);
    transpose_kernel<<<dim3(N_LAT / 32, D_MODEL / 32), dim3(32, 8)>>>(Wd);

    cudaFuncSetAttribute(gemm_mma, cudaFuncAttributeMaxDynamicSharedMemorySize, GEMM_SMEM);
    gemm_mma<<<dim3(N_LAT / 128, NROWS / 128), 256, GEMM_SMEM>>>(be, pre);

    cudaFuncSetAttribute(topk_kernel, cudaFuncAttributeMaxDynamicSharedMemorySize,
                         N_LAT * (int)sizeof(unsigned));
    topk_kernel<<<NROWS, 256, N_LAT * sizeof(unsigned)>>>(pre);

    refine_kernel<<<NROWS, 256>>>(x, We, be, latents);

    recon_kernel<<<NROWS, 256>>>(bd, recon);
}

// round 7
// speedup vs baseline: 4.2734x; 2.6617x over previous
#include <cuda_runtime.h>
#include <cuda_fp16.h>
#include <cstdint>

#define D_MODEL 768
#define N_LAT   16384
#define NROWS   8192
#define TOPK    32
#define NCAND   48
#define CAP     64

// ---------------- device scratch (no allocs allowed) ----------------
__device__ int   g_sel_idx[NROWS * TOPK];
__device__ float g_sel_val[NROWS * TOPK];
__device__ int   g_cand[NROWS * CAP];
__device__ int   g_nhi[NROWS];
__device__ int   g_neq[NROWS];
__device__ float g_Wt[(size_t)N_LAT * D_MODEL];           // W_dec transposed
__device__ __half g_x1[(size_t)NROWS * D_MODEL];          // fp16(x)
__device__ __half g_w1[(size_t)N_LAT * D_MODEL];          // fp16(W_enc)

__device__ __forceinline__ uint32_t smem_u32(const void* p) {
    uint32_t a;
    asm("{ .reg .u64 t; cvta.to.shared.u64 t, %1; cvt.u32.u64 %0, t; }" : "=r"(a) : "l"(p));
    return a;
}

// =====================================================================
// convert kernels
// =====================================================================
__global__ __launch_bounds__(256) void convert_x(const float* __restrict__ x)
{
    int i = blockIdx.x * 256 + threadIdx.x;
    float4 v = ((const float4*)x)[i];
    __half2 a = __halves2half2(__float2half_rn(v.x), __float2half_rn(v.y));
    __half2 b = __halves2half2(__float2half_rn(v.z), __float2half_rn(v.w));
    ((uint2*)g_x1)[i] = make_uint2(*(uint32_t*)&a, *(uint32_t*)&b);
}

__global__ __launch_bounds__(256) void convert_w(const float* __restrict__ W)
{
    int i = blockIdx.x * 256 + threadIdx.x;
    float4 v = ((const float4*)W)[i];
    __half2 a = __halves2half2(__float2half_rn(v.x), __float2half_rn(v.y));
    __half2 b = __halves2half2(__float2half_rn(v.z), __float2half_rn(v.w));
    ((uint2*)g_w1)[i] = make_uint2(*(uint32_t*)&a, *(uint32_t*)&b);
}

// =====================================================================
// GEMM1: pre = x @ W_enc^T + b_enc, fp16 MMA, fp32 accum
// CTA 128x128, BK=64, 8 warps (2x4, warp 64x32), 3-stage cp.async,
// 110.6KB smem -> 2 CTAs/SM.
// =====================================================================
#define GBK 64
#define ROWB 144
#define TILEB (128 * ROWB)             // 18432
#define STAGEB (2 * TILEB)             // A B
#define GSTAGES 3
#define GEMM_SMEM (GSTAGES * STAGEB)   // 110592

__device__ __forceinline__ void ldsm4(uint32_t& r0, uint32_t& r1, uint32_t& r2, uint32_t& r3,
                                      uint32_t addr) {
    asm volatile("ldmatrix.sync.aligned.m8n8.x4.shared.b16 {%0,%1,%2,%3}, [%4];"
                 : "=r"(r0), "=r"(r1), "=r"(r2), "=r"(r3) : "r"(addr));
}
__device__ __forceinline__ void mma16816(float* c, const uint32_t* a, const uint32_t* b) {
    asm volatile("mma.sync.aligned.m16n8k16.row.col.f32.f16.f16.f32 "
                 "{%0,%1,%2,%3}, {%4,%5,%6,%7}, {%8,%9}, {%0,%1,%2,%3};"
                 : "+f"(c[0]), "+f"(c[1]), "+f"(c[2]), "+f"(c[3])
                 : "r"(a[0]), "r"(a[1]), "r"(a[2]), "r"(a[3]), "r"(b[0]), "r"(b[1]));
}
__device__ __forceinline__ void cpasync16(uint32_t dst, const void* src) {
    asm volatile("cp.async.cg.shared.global [%0], [%1], 16;" :: "r"(dst), "l"(src));
}

__global__ __launch_bounds__(256, 2) void gemm_mma(
    const float* __restrict__ bias, float* __restrict__ C)
{
    extern __shared__ char sm[];
    const uint32_t sb = smem_u32(sm);
    const int tid = threadIdx.x;
    const int bm = blockIdx.y * 128;
    const int bn = blockIdx.x * 128;
    const int lane = tid & 31;
    const int warp = tid >> 5;
    const int wm = warp & 1;
    const int wn = warp >> 1;

    float acc[4][4][4];
#pragma unroll
    for (int i = 0; i < 4; i++)
#pragma unroll
        for (int j = 0; j < 4; j++)
#pragma unroll
            for (int q = 0; q < 4; q++) acc[i][j][q] = 0.f;

    const __half* ax = g_x1 + (size_t)bm * D_MODEL;
    const __half* bw = g_w1 + (size_t)bn * D_MODEL;

    auto load_stage = [&](int s, int c) {
        const int k0 = c * GBK;
#pragma unroll
        for (int i = 0; i < 8; ++i) {
            int idx = tid + i * 256;
            int t = idx >> 10;
            int rem = idx & 1023;
            int row = rem >> 3, ch = rem & 7;
            uint32_t dst = sb + s * STAGEB + t * TILEB + row * ROWB + ch * 16;
            const __half* base = (t == 0) ? ax : bw;
            cpasync16(dst, base + (size_t)row * D_MODEL + k0 + ch * 8);
        }
    };

    const int NCH = D_MODEL / GBK;   // 12
    load_stage(0, 0);
    asm volatile("cp.async.commit_group;");
    load_stage(1, 1);
    asm volatile("cp.async.commit_group;");

    const uint32_t a_row = (uint32_t)(wm * 64 + (lane & 7) + ((lane >> 3) & 1) * 8);
    const uint32_t a_off = a_row * ROWB + ((lane >> 4) * 16);
    const uint32_t b_row = (uint32_t)(wn * 32 + (lane & 7) + ((lane >> 4) & 1) * 8);
    const uint32_t b_off = b_row * ROWB + (((lane >> 3) & 1) * 16);

    for (int c = 0; c < NCH; ++c) {
        asm volatile("cp.async.wait_group %0;" :: "n"(1));
        __syncthreads();
        if (c + 2 < NCH) load_stage((c + 2) % GSTAGES, c + 2);
        asm volatile("cp.async.commit_group;");

        const uint32_t stg = sb + (c % GSTAGES) * STAGEB;
#pragma unroll
        for (int kg = 0; kg < 4; ++kg) {
            const uint32_t kgo = kg * 32;
            uint32_t af[4][4], bf[4][2];
#pragma unroll
            for (int mt = 0; mt < 4; ++mt)
                ldsm4(af[mt][0], af[mt][1], af[mt][2], af[mt][3],
                      stg + 0 * TILEB + a_off + mt * 16 * ROWB + kgo);
#pragma unroll
            for (int q = 0; q < 2; ++q)
                ldsm4(bf[2 * q][0], bf[2 * q][1], bf[2 * q + 1][0], bf[2 * q + 1][1],
                      stg + 1 * TILEB + b_off + q * 16 * ROWB + kgo);
#pragma unroll
            for (int mt = 0; mt < 4; ++mt)
#pragma unroll
                for (int nt = 0; nt < 4; ++nt) mma16816(acc[mt][nt], af[mt], bf[nt]);
        }
    }

#pragma unroll
    for (int nt = 0; nt < 4; ++nt) {
        const int col = bn + wn * 32 + nt * 8 + (lane & 3) * 2;
        const float2 bv = *(const float2*)&bias[col];
#pragma unroll
        for (int mt = 0; mt < 4; ++mt) {
            const int row = bm + wm * 64 + mt * 16 + (lane >> 2);
            float2 v0 = make_float2(acc[mt][nt][0] + bv.x, acc[mt][nt][1] + bv.y);
            float2 v1 = make_float2(acc[mt][nt][2] + bv.x, acc[mt][nt][3] + bv.y);
            *(float2*)&C[(size_t)row * N_LAT + col] = v0;
            *(float2*)&C[(size_t)(row + 8) * N_LAT + col] = v1;
        }
    }
}

// =====================================================================
// topk v2: per-row candidate superset (>= NCAND) via 2-level radix bins.
// 512 thr, float4 loads, parallel suffix scan, no serial kth-search.
// =====================================================================
__global__ __launch_bounds__(512) void topk_kernel(const float* __restrict__ pre)
{
    extern __shared__ unsigned su[];           // 16384 keys
    __shared__ unsigned hist[2048];
    __shared__ int csum[512];
    __shared__ int s_t1, s_cab, s_b, s_c, s_target;
    __shared__ int s_nhi, s_neq;

    const int row = blockIdx.x;
    const int tid = threadIdx.x;
    const float* prow = pre + (size_t)row * N_LAT;

    for (int i = tid; i < 2048; i += 512) hist[i] = 0u;
    if (tid == 0) { s_nhi = 0; s_neq = 0; s_target = NCAND; }
    __syncthreads();

    // load + key-map + level-1 histogram (top 11 bits)
    for (int i = tid; i < N_LAT / 4; i += 512) {
        float4 v = ((const float4*)prow)[i];
        unsigned b0 = __float_as_uint(v.x), b1 = __float_as_uint(v.y);
        unsigned b2 = __float_as_uint(v.z), b3 = __float_as_uint(v.w);
        unsigned u0 = (b0 & 0x80000000u) ? ~b0 : (b0 | 0x80000000u);
        unsigned u1 = (b1 & 0x80000000u) ? ~b1 : (b1 | 0x80000000u);
        unsigned u2 = (b2 & 0x80000000u) ? ~b2 : (b2 | 0x80000000u);
        unsigned u3 = (b3 & 0x80000000u) ? ~b3 : (b3 | 0x80000000u);
        *(uint4*)&su[i * 4] = make_uint4(u0, u1, u2, u3);
        atomicAdd(&hist[u0 >> 21], 1u);
        atomicAdd(&hist[u1 >> 21], 1u);
        atomicAdd(&hist[u2 >> 21], 1u);
        atomicAdd(&hist[u3 >> 21], 1u);
    }

    unsigned P;   // 21-bit threshold prefix
#pragma unroll
    for (int pass = 0; pass < 2; ++pass) {
        __syncthreads();
        const int target = s_target;
        // chunk sums: 4 bins per thread
        int cs = (int)hist[tid * 4] + (int)hist[tid * 4 + 1]
               + (int)hist[tid * 4 + 2] + (int)hist[tid * 4 + 3];
        csum[tid] = cs;
        __syncthreads();
        // suffix sum (Hillis-Steele)
#pragma unroll
        for (int off = 1; off < 512; off <<= 1) {
            int v = csum[tid] + ((tid + off < 512) ? csum[tid + off] : 0);
            __syncthreads();
            csum[tid] = v;
            __syncthreads();
        }
        // find chunk where suffix crosses target
        int nxt = (tid + 1 < 512) ? csum[tid + 1] : 0;
        if (csum[tid] >= target && nxt < target) { s_t1 = tid; s_cab = nxt; }
        __syncthreads();
        if (tid == 0) {
            int t1 = s_t1, cum = s_cab, b = 0, c = 0;
            for (int bb = t1 * 4 + 3;; --bb) {
                if (cum + (int)hist[bb] >= target) { b = bb; c = cum; break; }
                cum += (int)hist[bb];
            }
            s_b = b; s_c = c;
        }
        __syncthreads();
        if (pass == 0) {
            const int b1 = s_b;
            const int c1 = s_c;
            if (tid == 0) s_target = NCAND - c1;
            __syncthreads();
            // level-2 histogram within bin b1 (next 11 bits)
            for (int i = tid; i < 2048; i += 512) hist[i] = 0u;
            __syncthreads();
            for (int i = tid; i < N_LAT; i += 512) {
                unsigned u = su[i];
                if ((int)(u >> 21) == b1) atomicAdd(&hist[(u >> 10) & 2047u], 1u);
            }
            P = (unsigned)b1 << 11;    // partial; completed after pass 1
        }
    }
    P = ((su[0] , P) & 0xFFFFF800u) | (unsigned)s_b;   // P = (b1<<11)|b2
    __syncthreads();

    // collect: strictly greater from front, equals from back
    for (int i = tid; i < N_LAT; i += 512) {
        unsigned hi = su[i] >> 10;
        if (hi > P) {
            int p = atomicAdd(&s_nhi, 1);
            if (p < CAP) g_cand[row * CAP + p] = i;
        } else if (hi == P) {
            int p = atomicAdd(&s_neq, 1);
            if (p < CAP) g_cand[row * CAP + (CAP - 1 - p)] = i;
        }
    }
    __syncthreads();
    if (tid == 0) {
        g_nhi[row] = s_nhi < CAP ? s_nhi : CAP;
        g_neq[row] = s_neq < CAP ? s_neq : CAP;
    }
}

// =====================================================================
// refine: compensated-fp32 exact dots for <=CAP candidates, top-32 select
// =====================================================================
__global__ __launch_bounds__(256) void refine_kernel(
    const float* __restrict__ x, const float* __restrict__ We,
    const float* __restrict__ be, float* __restrict__ latents)
{
    __shared__ float xs[D_MODEL];
    __shared__ float cv[CAP];
    __shared__ int   ci[CAP];
    const int row = blockIdx.x;
    const int tid = threadIdx.x;
    const int lane = tid & 31, warp = tid >> 5;

    for (int j = tid; j < D_MODEL / 4; j += 256)
        *(float4*)&xs[j * 4] = ((const float4*)(x + (size_t)row * D_MODEL))[j];
    if (tid < CAP) {
        int nhi = g_nhi[row], neq = g_neq[row];
        bool valid = (tid < nhi) || (tid >= CAP - neq);
        ci[tid] = valid ? g_cand[row * CAP + tid] : -1;
        cv[tid] = -1e30f;
    }
    __syncthreads();

    for (int c = warp; c < CAP; c += 8) {
        const int idx = ci[c];
        if (idx < 0) continue;
        const float* wr = We + (size_t)idx * D_MODEL;
        float s = 0.f, e = 0.f;
#pragma unroll 4
        for (int j = lane; j < D_MODEL; j += 32) {
            float a = xs[j], b = wr[j];
            float p = a * b;
            float pe = fmaf(a, b, -p);
            float t = s + p;
            float z = t - s;
            e += ((s - (t - z)) + (p - z)) + pe;
            s = t;
        }
#pragma unroll
        for (int o = 16; o > 0; o >>= 1) {
            float so = __shfl_down_sync(0xffffffffu, s, o);
            float eo = __shfl_down_sync(0xffffffffu, e, o);
            float t = s + so;
            float z = t - s;
            e += ((s - (t - z)) + (so - z)) + eo;
            s = t;
        }
        if (lane == 0) {
            float bb = be[idx];
            float t = s + bb;
            float z = t - s;
            e += (s - (t - z)) + (bb - z);
            cv[c] = t + e;
        }
    }
    __syncthreads();

    if (tid < CAP) {
        const int idx = ci[tid];
        if (idx >= 0) {
            const float v = cv[tid];
            int r = 0;
#pragma unroll
            for (int j = 0; j < CAP; ++j) {
                float u = cv[j];
                r += (u > v) || (u == v && ci[j] < idx && ci[j] >= 0);
            }
            if (r < TOPK) {
                float rv = v > 0.f ? v : 0.f;
                latents[(size_t)row * N_LAT + idx] = rv;
                g_sel_idx[row * TOPK + r] = idx;
                g_sel_val[row * TOPK + r] = rv;
            }
        }
    }
}

// ---------------- W_dec transpose ----------------
__global__ void transpose_kernel(const float* __restrict__ W)
{
    __shared__ float t[32][33];
    const int j0 = blockIdx.x * 32;
    const int d0 = blockIdx.y * 32;
    const int tx = threadIdx.x;
    const int ty0 = threadIdx.y;
#pragma unroll
    for (int s = 0; s < 32; s += 8) {
        int ty = ty0 + s;
        t[ty][tx] = W[(size_t)(d0 + ty) * N_LAT + j0 + tx];
    }
    __syncthreads();
#pragma unroll
    for (int s = 0; s < 32; s += 8) {
        int ty = ty0 + s;
        g_Wt[(size_t)(j0 + ty) * D_MODEL + d0 + tx] = t[tx][ty];
    }
}

// ---------------- sparse decode ----------------
__global__ __launch_bounds__(256) void recon_kernel(
    const float* __restrict__ b_dec, float* __restrict__ recon)
{
    __shared__ int sidx[TOPK];
    __shared__ float sval[TOPK];
    const int row = blockIdx.x;
    const int tid = threadIdx.x;
    if (tid < TOPK) {
        sidx[tid] = g_sel_idx[row * TOPK + tid];
        sval[tid] = g_sel_val[row * TOPK + tid];
    }
    __syncthreads();
    float a0 = 0.f, a1 = 0.f, a2 = 0.f;
#pragma unroll 4
    for (int k = 0; k < TOPK; k++) {
        float v = sval[k];
        const float* w = &g_Wt[(size_t)sidx[k] * D_MODEL];
        a0 += v * w[tid];
        a1 += v * w[tid + 256];
        a2 += v * w[tid + 512];
    }
    const size_t o = (size_t)row * D_MODEL;
    recon[o + tid]       = a0 + b_dec[tid];
    recon[o + tid + 256] = a1 + b_dec[tid + 256];
    recon[o + tid + 512] = a2 + b_dec[tid + 512];
}

// ---------------- launch ----------------
extern "C" void kernel_launch(void* const* d_in, const int* in_sizes, int n_in,
                              void* d_out, int out_size)
{
    const float* x  = (const float*)d_in[0];
    const float* We = (const float*)d_in[1];
    const float* be = (const float*)d_in[2];
    const float* Wd = (const float*)d_in[3];
    const float* bd = (const float*)d_in[4];

    float* out     = (float*)d_out;
    float* latents = out;
    float* recon   = out + (size_t)NROWS * N_LAT;
    float* pre     = recon + (size_t)NROWS * D_MODEL;

    cudaMemsetAsync(latents, 0, (size_t)NROWS * N_LAT * sizeof(float));

    convert_x<<<NROWS * D_MODEL / 4 / 256, 256>>>(x);
    convert_w<<<N_LAT * D_MODEL / 4 / 256, 256>>>(We);
    transpose_kernel<<<dim3(N_LAT / 32, D_MODEL / 32), dim3(32, 8)>>>(Wd);

    cudaFuncSetAttribute(gemm_mma, cudaFuncAttributeMaxDynamicSharedMemorySize, GEMM_SMEM);
    gemm_mma<<<dim3(N_LAT / 128, NROWS / 128), 256, GEMM_SMEM>>>(be, pre);

    cudaFuncSetAttribute(topk_kernel, cudaFuncAttributeMaxDynamicSharedMemorySize,
                         N_LAT * (int)sizeof(unsigned));
    topk_kernel<<<NROWS, 512, N_LAT * sizeof(unsigned)>>>(pre);

    refine_kernel<<<NROWS, 256>>>(x, We, be, latents);

    recon_kernel<<<NROWS, 256>>>(bd, recon);
}

// round 8
// speedup vs baseline: 4.4630x; 1.0444x over previous
#include <cuda_runtime.h>
#include <cuda_fp16.h>
#include <cstdint>

#define D_MODEL 768
#define N_LAT   16384
#define NROWS   8192
#define TOPK    32
#define NCAND   48
#define CAP     64

// ---------------- device scratch (no allocs allowed) ----------------
__device__ int   g_sel_idx[NROWS * TOPK];
__device__ float g_sel_val[NROWS * TOPK];
__device__ int   g_cand[NROWS * CAP];
__device__ int   g_nhi[NROWS];
__device__ int   g_neq[NROWS];
__device__ float g_Wt[(size_t)N_LAT * D_MODEL];           // W_dec transposed
__device__ __half g_x1[(size_t)NROWS * D_MODEL];          // fp16(x)
__device__ __half g_w1[(size_t)N_LAT * D_MODEL];          // fp16(W_enc)

__device__ __forceinline__ uint32_t smem_u32(const void* p) {
    uint32_t a;
    asm("{ .reg .u64 t; cvta.to.shared.u64 t, %1; cvt.u32.u64 %0, t; }" : "=r"(a) : "l"(p));
    return a;
}

// =====================================================================
// convert kernels
// =====================================================================
__global__ __launch_bounds__(256) void convert_x(const float* __restrict__ x)
{
    int i = blockIdx.x * 256 + threadIdx.x;
    float4 v = ((const float4*)x)[i];
    __half2 a = __halves2half2(__float2half_rn(v.x), __float2half_rn(v.y));
    __half2 b = __halves2half2(__float2half_rn(v.z), __float2half_rn(v.w));
    ((uint2*)g_x1)[i] = make_uint2(*(uint32_t*)&a, *(uint32_t*)&b);
}

__global__ __launch_bounds__(256) void convert_w(const float* __restrict__ W)
{
    int i = blockIdx.x * 256 + threadIdx.x;
    float4 v = ((const float4*)W)[i];
    __half2 a = __halves2half2(__float2half_rn(v.x), __float2half_rn(v.y));
    __half2 b = __halves2half2(__float2half_rn(v.z), __float2half_rn(v.w));
    ((uint2*)g_w1)[i] = make_uint2(*(uint32_t*)&a, *(uint32_t*)&b);
}

// =====================================================================
// GEMM1: pre = x @ W_enc^T + b_enc, fp16 MMA, fp32 accum
// CTA 128x128, BK=64, 8 warps (2x4, warp 64x32), 3-stage cp.async,
// 110.6KB smem -> 2 CTAs/SM. LDSM/MMA interleaved for latency hiding.
// =====================================================================
#define GBK 64
#define ROWB 144
#define TILEB (128 * ROWB)             // 18432
#define STAGEB (2 * TILEB)             // A B
#define GSTAGES 3
#define GEMM_SMEM (GSTAGES * STAGEB)   // 110592

__device__ __forceinline__ void ldsm4(uint32_t& r0, uint32_t& r1, uint32_t& r2, uint32_t& r3,
                                      uint32_t addr) {
    asm volatile("ldmatrix.sync.aligned.m8n8.x4.shared.b16 {%0,%1,%2,%3}, [%4];"
                 : "=r"(r0), "=r"(r1), "=r"(r2), "=r"(r3) : "r"(addr));
}
__device__ __forceinline__ void mma16816(float* c, const uint32_t* a, const uint32_t* b) {
    asm volatile("mma.sync.aligned.m16n8k16.row.col.f32.f16.f16.f32 "
                 "{%0,%1,%2,%3}, {%4,%5,%6,%7}, {%8,%9}, {%0,%1,%2,%3};"
                 : "+f"(c[0]), "+f"(c[1]), "+f"(c[2]), "+f"(c[3])
                 : "r"(a[0]), "r"(a[1]), "r"(a[2]), "r"(a[3]), "r"(b[0]), "r"(b[1]));
}
__device__ __forceinline__ void cpasync16(uint32_t dst, const void* src) {
    asm volatile("cp.async.cg.shared.global [%0], [%1], 16;" :: "r"(dst), "l"(src));
}

__global__ __launch_bounds__(256, 2) void gemm_mma(
    const float* __restrict__ bias, float* __restrict__ C)
{
    extern __shared__ char sm[];
    const uint32_t sb = smem_u32(sm);
    const int tid = threadIdx.x;
    const int bm = blockIdx.y * 128;
    const int bn = blockIdx.x * 128;
    const int lane = tid & 31;
    const int warp = tid >> 5;
    const int wm = warp & 1;
    const int wn = warp >> 1;

    float acc[4][4][4];
#pragma unroll
    for (int i = 0; i < 4; i++)
#pragma unroll
        for (int j = 0; j < 4; j++)
#pragma unroll
            for (int q = 0; q < 4; q++) acc[i][j][q] = 0.f;

    const __half* ax = g_x1 + (size_t)bm * D_MODEL;
    const __half* bw = g_w1 + (size_t)bn * D_MODEL;

    auto load_stage = [&](int s, int c) {
        const int k0 = c * GBK;
#pragma unroll
        for (int i = 0; i < 8; ++i) {
            int idx = tid + i * 256;
            int t = idx >> 10;
            int rem = idx & 1023;
            int row = rem >> 3, ch = rem & 7;
            uint32_t dst = sb + s * STAGEB + t * TILEB + row * ROWB + ch * 16;
            const __half* base = (t == 0) ? ax : bw;
            cpasync16(dst, base + (size_t)row * D_MODEL + k0 + ch * 8);
        }
    };

    const int NCH = D_MODEL / GBK;   // 12
    load_stage(0, 0);
    asm volatile("cp.async.commit_group;");
    load_stage(1, 1);
    asm volatile("cp.async.commit_group;");

    const uint32_t a_row = (uint32_t)(wm * 64 + (lane & 7) + ((lane >> 3) & 1) * 8);
    const uint32_t a_off = a_row * ROWB + ((lane >> 4) * 16);
    const uint32_t b_row = (uint32_t)(wn * 32 + (lane & 7) + ((lane >> 4) & 1) * 8);
    const uint32_t b_off = b_row * ROWB + (((lane >> 3) & 1) * 16);

    for (int c = 0; c < NCH; ++c) {
        asm volatile("cp.async.wait_group %0;" :: "n"(1));
        __syncthreads();
        if (c + 2 < NCH) load_stage((c + 2) % GSTAGES, c + 2);
        asm volatile("cp.async.commit_group;");

        const uint32_t stg = sb + (c % GSTAGES) * STAGEB;
#pragma unroll
        for (int kg = 0; kg < 4; ++kg) {
            const uint32_t kgo = kg * 32;
            uint32_t af[4][4], bf[4][2];
            // B fragments first (needed by every MMA)
#pragma unroll
            for (int q = 0; q < 2; ++q)
                ldsm4(bf[2 * q][0], bf[2 * q][1], bf[2 * q + 1][0], bf[2 * q + 1][1],
                      stg + 1 * TILEB + b_off + q * 16 * ROWB + kgo);
            // A fragment for mt=0
            ldsm4(af[0][0], af[0][1], af[0][2], af[0][3],
                  stg + 0 * TILEB + a_off + 0 * 16 * ROWB + kgo);
            // interleave: issue af[mt+1] load, then MMAs for mt
#pragma unroll
            for (int mt = 0; mt < 4; ++mt) {
                if (mt < 3)
                    ldsm4(af[mt + 1][0], af[mt + 1][1], af[mt + 1][2], af[mt + 1][3],
                          stg + 0 * TILEB + a_off + (mt + 1) * 16 * ROWB + kgo);
#pragma unroll
                for (int nt = 0; nt < 4; ++nt) mma16816(acc[mt][nt], af[mt], bf[nt]);
            }
        }
    }

#pragma unroll
    for (int nt = 0; nt < 4; ++nt) {
        const int col = bn + wn * 32 + nt * 8 + (lane & 3) * 2;
        const float2 bv = *(const float2*)&bias[col];
#pragma unroll
        for (int mt = 0; mt < 4; ++mt) {
            const int row = bm + wm * 64 + mt * 16 + (lane >> 2);
            float2 v0 = make_float2(acc[mt][nt][0] + bv.x, acc[mt][nt][1] + bv.y);
            float2 v1 = make_float2(acc[mt][nt][2] + bv.x, acc[mt][nt][3] + bv.y);
            *(float2*)&C[(size_t)row * N_LAT + col] = v0;
            *(float2*)&C[(size_t)(row + 8) * N_LAT + col] = v1;
        }
    }
}

// =====================================================================
// topk: candidate superset via 2-level radix bins + fused latents zeroing
// =====================================================================
__global__ __launch_bounds__(512) void topk_kernel(const float* __restrict__ pre,
                                                   float* __restrict__ latents)
{
    extern __shared__ unsigned su[];           // 16384 keys
    __shared__ unsigned hist[2048];
    __shared__ int csum[512];
    __shared__ int s_t1, s_cab, s_b, s_c, s_target;
    __shared__ int s_nhi, s_neq;

    const int row = blockIdx.x;
    const int tid = threadIdx.x;
    const float* prow = pre + (size_t)row * N_LAT;
    float* lrow = latents + (size_t)row * N_LAT;

    for (int i = tid; i < 2048; i += 512) hist[i] = 0u;
    if (tid == 0) { s_nhi = 0; s_neq = 0; s_target = NCAND; }
    __syncthreads();

    // load + key-map + level-1 histogram; zero latents row on the way
    const float4 z4 = make_float4(0.f, 0.f, 0.f, 0.f);
    for (int i = tid; i < N_LAT / 4; i += 512) {
        float4 v = ((const float4*)prow)[i];
        ((float4*)lrow)[i] = z4;
        unsigned b0 = __float_as_uint(v.x), b1 = __float_as_uint(v.y);
        unsigned b2 = __float_as_uint(v.z), b3 = __float_as_uint(v.w);
        unsigned u0 = (b0 & 0x80000000u) ? ~b0 : (b0 | 0x80000000u);
        unsigned u1 = (b1 & 0x80000000u) ? ~b1 : (b1 | 0x80000000u);
        unsigned u2 = (b2 & 0x80000000u) ? ~b2 : (b2 | 0x80000000u);
        unsigned u3 = (b3 & 0x80000000u) ? ~b3 : (b3 | 0x80000000u);
        *(uint4*)&su[i * 4] = make_uint4(u0, u1, u2, u3);
        atomicAdd(&hist[u0 >> 21], 1u);
        atomicAdd(&hist[u1 >> 21], 1u);
        atomicAdd(&hist[u2 >> 21], 1u);
        atomicAdd(&hist[u3 >> 21], 1u);
    }

    unsigned P = 0;   // threshold prefix (b1<<11 | b2)
#pragma unroll
    for (int pass = 0; pass < 2; ++pass) {
        __syncthreads();
        const int target = s_target;
        int cs = (int)hist[tid * 4] + (int)hist[tid * 4 + 1]
               + (int)hist[tid * 4 + 2] + (int)hist[tid * 4 + 3];
        csum[tid] = cs;
        __syncthreads();
#pragma unroll
        for (int off = 1; off < 512; off <<= 1) {
            int v = csum[tid] + ((tid + off < 512) ? csum[tid + off] : 0);
            __syncthreads();
            csum[tid] = v;
            __syncthreads();
        }
        int nxt = (tid + 1 < 512) ? csum[tid + 1] : 0;
        if (csum[tid] >= target && nxt < target) { s_t1 = tid; s_cab = nxt; }
        __syncthreads();
        if (tid == 0) {
            int t1 = s_t1, cum = s_cab, b = 0, c = 0;
            for (int bb = t1 * 4 + 3;; --bb) {
                if (cum + (int)hist[bb] >= target) { b = bb; c = cum; break; }
                cum += (int)hist[bb];
            }
            s_b = b; s_c = c;
        }
        __syncthreads();
        if (pass == 0) {
            const int b1 = s_b;
            const int c1 = s_c;
            if (tid == 0) s_target = NCAND - c1;
            __syncthreads();
            for (int i = tid; i < 2048; i += 512) hist[i] = 0u;
            __syncthreads();
            for (int i = tid; i < N_LAT; i += 512) {
                unsigned u = su[i];
                if ((int)(u >> 21) == b1) atomicAdd(&hist[(u >> 10) & 2047u], 1u);
            }
            P = (unsigned)b1 << 11;
        }
    }
    P |= (unsigned)s_b;   // P = (b1<<11)|b2
    __syncthreads();

    // collect: strictly greater from front, equals from back
    for (int i = tid; i < N_LAT; i += 512) {
        unsigned hi = su[i] >> 10;
        if (hi > P) {
            int p = atomicAdd(&s_nhi, 1);
            if (p < CAP) g_cand[row * CAP + p] = i;
        } else if (hi == P) {
            int p = atomicAdd(&s_neq, 1);
            if (p < CAP) g_cand[row * CAP + (CAP - 1 - p)] = i;
        }
    }
    __syncthreads();
    if (tid == 0) {
        g_nhi[row] = s_nhi < CAP ? s_nhi : CAP;
        g_neq[row] = s_neq < CAP ? s_neq : CAP;
    }
}

// =====================================================================
// refine: compensated-fp32 exact dots for <=CAP candidates, top-32 select
// =====================================================================
__global__ __launch_bounds__(256) void refine_kernel(
    const float* __restrict__ x, const float* __restrict__ We,
    const float* __restrict__ be, float* __restrict__ latents)
{
    __shared__ float4 xs4[D_MODEL / 4];
    __shared__ float cv[CAP];
    __shared__ int   ci[CAP];
    const int row = blockIdx.x;
    const int tid = threadIdx.x;
    const int lane = tid & 31, warp = tid >> 5;

    for (int j = tid; j < D_MODEL / 4; j += 256)
        xs4[j] = ((const float4*)(x + (size_t)row * D_MODEL))[j];
    if (tid < CAP) {
        int nhi = g_nhi[row], neq = g_neq[row];
        bool valid = (tid < nhi) || (tid >= CAP - neq);
        ci[tid] = valid ? g_cand[row * CAP + tid] : -1;
        cv[tid] = -1e30f;
    }
    __syncthreads();

    for (int c = warp; c < CAP; c += 8) {
        const int idx = ci[c];
        if (idx < 0) continue;
        const float4* wr = (const float4*)(We + (size_t)idx * D_MODEL);
        float s = 0.f, e = 0.f;
#pragma unroll
        for (int it = 0; it < D_MODEL / 128; ++it) {   // 6
            float4 w = wr[lane + it * 32];
            float4 a = xs4[lane + it * 32];
            float av[4] = {a.x, a.y, a.z, a.w};
            float wv[4] = {w.x, w.y, w.z, w.w};
#pragma unroll
            for (int q = 0; q < 4; ++q) {
                float p = av[q] * wv[q];
                float pe = fmaf(av[q], wv[q], -p);
                float t = s + p;
                float z = t - s;
                e += ((s - (t - z)) + (p - z)) + pe;
                s = t;
            }
        }
#pragma unroll
        for (int o = 16; o > 0; o >>= 1) {
            float so = __shfl_down_sync(0xffffffffu, s, o);
            float eo = __shfl_down_sync(0xffffffffu, e, o);
            float t = s + so;
            float z = t - s;
            e += ((s - (t - z)) + (so - z)) + eo;
            s = t;
        }
        if (lane == 0) {
            float bb = be[idx];
            float t = s + bb;
            float z = t - s;
            e += (s - (t - z)) + (bb - z);
            cv[c] = t + e;
        }
    }
    __syncthreads();

    if (tid < CAP) {
        const int idx = ci[tid];
        if (idx >= 0) {
            const float v = cv[tid];
            int r = 0;
#pragma unroll
            for (int j = 0; j < CAP; ++j) {
                float u = cv[j];
                r += (u > v) || (u == v && ci[j] < idx && ci[j] >= 0);
            }
            if (r < TOPK) {
                float rv = v > 0.f ? v : 0.f;
                latents[(size_t)row * N_LAT + idx] = rv;
                g_sel_idx[row * TOPK + r] = idx;
                g_sel_val[row * TOPK + r] = rv;
            }
        }
    }
}

// ---------------- W_dec transpose ----------------
__global__ void transpose_kernel(const float* __restrict__ W)
{
    __shared__ float t[32][33];
    const int j0 = blockIdx.x * 32;
    const int d0 = blockIdx.y * 32;
    const int tx = threadIdx.x;
    const int ty0 = threadIdx.y;
#pragma unroll
    for (int s = 0; s < 32; s += 8) {
        int ty = ty0 + s;
        t[ty][tx] = W[(size_t)(d0 + ty) * N_LAT + j0 + tx];
    }
    __syncthreads();
#pragma unroll
    for (int s = 0; s < 32; s += 8) {
        int ty = ty0 + s;
        g_Wt[(size_t)(j0 + ty) * D_MODEL + d0 + tx] = t[tx][ty];
    }
}

// ---------------- sparse decode ----------------
__global__ __launch_bounds__(256) void recon_kernel(
    const float* __restrict__ b_dec, float* __restrict__ recon)
{
    __shared__ int sidx[TOPK];
    __shared__ float sval[TOPK];
    const int row = blockIdx.x;
    const int tid = threadIdx.x;
    if (tid < TOPK) {
        sidx[tid] = g_sel_idx[row * TOPK + tid];
        sval[tid] = g_sel_val[row * TOPK + tid];
    }
    __syncthreads();
    float a0 = 0.f, a1 = 0.f, a2 = 0.f;
#pragma unroll 4
    for (int k = 0; k < TOPK; k++) {
        float v = sval[k];
        const float* w = &g_Wt[(size_t)sidx[k] * D_MODEL];
        a0 += v * w[tid];
        a1 += v * w[tid + 256];
        a2 += v * w[tid + 512];
    }
    const size_t o = (size_t)row * D_MODEL;
    recon[o + tid]       = a0 + b_dec[tid];
    recon[o + tid + 256] = a1 + b_dec[tid + 256];
    recon[o + tid + 512] = a2 + b_dec[tid + 512];
}

// ---------------- launch ----------------
extern "C" void kernel_launch(void* const* d_in, const int* in_sizes, int n_in,
                              void* d_out, int out_size)
{
    const float* x  = (const float*)d_in[0];
    const float* We = (const float*)d_in[1];
    const float* be = (const float*)d_in[2];
    const float* Wd = (const float*)d_in[3];
    const float* bd = (const float*)d_in[4];

    float* out     = (float*)d_out;
    float* latents = out;
    float* recon   = out + (size_t)NROWS * N_LAT;
    float* pre     = recon + (size_t)NROWS * D_MODEL;

    convert_x<<<NROWS * D_MODEL / 4 / 256, 256>>>(x);
    convert_w<<<N_LAT * D_MODEL / 4 / 256, 256>>>(We);
    transpose_kernel<<<dim3(N_LAT / 32, D_MODEL / 32), dim3(32, 8)>>>(Wd);

    cudaFuncSetAttribute(gemm_mma, cudaFuncAttributeMaxDynamicSharedMemorySize, GEMM_SMEM);
    gemm_mma<<<dim3(N_LAT / 128, NROWS / 128), 256, GEMM_SMEM>>>(be, pre);

    cudaFuncSetAttribute(topk_kernel, cudaFuncAttributeMaxDynamicSharedMemorySize,
                         N_LAT * (int)sizeof(unsigned));
    topk_kernel<<<NROWS, 512, N_LAT * sizeof(unsigned)>>>(pre, latents);

    refine_kernel<<<NROWS, 256>>>(x, We, be, latents);

    recon_kernel<<<NROWS, 256>>>(bd, recon);
}